// round 12
// baseline (speedup 1.0000x reference)
#include <cuda_runtime.h>
#include <cuda_fp16.h>
#include <cstdint>
#include <math.h>

#define NN   50000
#define EE   500000
#define KIN  512
#define HH   4
#define CC   64
#define HC   256
#define ET   (EE + NN)

#define NEG_SLOPE 0.2f

#define SCAN_TILE 4096
#define NBLK ((NN + SCAN_TILE - 1) / SCAN_TILE)   // 13

// ---------------- scratch (no allocations allowed) ----------------
__device__ __half g_Wh[HC * KIN];       // W transposed fp16 [N=256][K=512]
__device__ __half g_h16[NN * HC];       // projected features, fp16 copy for gather
__device__ float g_asrc[NN * HH];       // per-node src attn scores [N, H]
__device__ float g_adst[NN * HH];       // per-node dst attn scores [N, H]
__device__ int   g_deg[NN];             // in-degree (incl. self loop)
__device__ int   g_bsum[NBLK];          // per-scan-block degree sums
__device__ int   g_bbase[NBLK];         // exclusive prefix of block sums
__device__ int   g_off[NN + 1];         // CSR offsets
__device__ int   g_cur[NN];             // scatter cursors
__device__ int   g_srcid[ET];           // CSR: source node per incoming edge

__device__ __forceinline__ void mma_f16(float* c, const uint32_t* a, const uint32_t* b) {
    asm volatile(
        "mma.sync.aligned.m16n8k16.row.col.f32.f16.f16.f32 "
        "{%0,%1,%2,%3}, {%4,%5,%6,%7}, {%8,%9}, {%0,%1,%2,%3};"
        : "+f"(c[0]), "+f"(c[1]), "+f"(c[2]), "+f"(c[3])
        : "r"(a[0]), "r"(a[1]), "r"(a[2]), "r"(a[3]), "r"(b[0]), "r"(b[1]));
}

__device__ __forceinline__ uint32_t f16x2(float x, float y) {
    uint32_t d;
    asm("cvt.rn.f16x2.f32 %0, %1, %2;" : "=r"(d) : "f"(y), "f"(x));
    return d;
}

__device__ __forceinline__ uint32_t smem_u32(const void* p) {
    uint32_t a;
    asm("{ .reg .u64 t; cvta.to.shared.u64 t, %1; cvt.u32.u64 %0, t; }" : "=r"(a) : "l"(p));
    return a;
}
__device__ __forceinline__ void cp_async16(uint32_t dst, const void* src, int sz) {
    asm volatile("cp.async.cg.shared.global [%0], [%1], 16, %2;"
                 :: "r"(dst), "l"(src), "r"(sz) : "memory");
}
#define CP_COMMIT() asm volatile("cp.async.commit_group;" ::: "memory")
#define CP_WAIT1()  asm volatile("cp.async.wait_group 1;" ::: "memory")

// ---------------- 0) W transpose -> fp16 ----------------
__global__ void wt_kernel(const float* __restrict__ W) {
    int idx = blockIdx.x * blockDim.x + threadIdx.x;
    if (idx < KIN * HC) {
        int k = idx >> 8;
        int n = idx & 255;
        g_Wh[n * KIN + k] = __float2half_rn(W[idx]);
    }
}

// ---------------- 1) GEMM + fused attn scalars (M=128 x N=256 tile, 512 thr) ----------------
#define BK 32
#define NSTAGE 3
#define A_PITCH_F 40
#define B_PITCH_W 20
#define A_BYTES (128 * 160)              // 20480
#define B_OFF   A_BYTES
#define STG_BYTES (A_BYTES + 256 * 80)   // 40960
#define GEMM_SMEM (NSTAGE * STG_BYTES)   // 122880
#define NKS (KIN / BK)   // 16

__global__ __launch_bounds__(512, 1) void mma_gemm_kernel(const float* __restrict__ x,
                                                          const float* __restrict__ att_src,
                                                          const float* __restrict__ att_dst) {
    extern __shared__ char smem[];
    const uint32_t sb = smem_u32(smem);

    const int tid  = threadIdx.x;
    const int lane = tid & 31;
    const int wid  = tid >> 5;        // 0..15
    const int wm   = wid & 3;         // M position (32 rows each)
    const int wn   = wid >> 2;        // N position (64 cols each) == head
    const int m0   = blockIdx.x * 128;
    const int r4   = lane >> 2;
    const int c4   = lane & 3;

    // A: 1024 16B-chunks per stage -> 2/thread. row = c>>3 (0..127), q = c&7.
    int arow[2], aq[2];
    const float* gA[2];
    int szA[2];
    uint32_t dA[2];
#pragma unroll
    for (int i = 0; i < 2; i++) {
        int c = i * 512 + tid;
        arow[i] = c >> 3; aq[i] = c & 7;
        gA[i] = x + (size_t)(m0 + arow[i]) * KIN + aq[i] * 4;
        szA[i] = (m0 + arow[i] < NN) ? 16 : 0;
        dA[i] = (uint32_t)(arow[i] * 160 + aq[i] * 16);
    }
    // B: 1024 16B-chunks per stage -> 2/thread. row = c>>2 (0..255), q = c&3.
    int brow[2], bq[2];
    const __half* gB[2];
    uint32_t dB[2];
#pragma unroll
    for (int i = 0; i < 2; i++) {
        int c = i * 512 + tid;
        brow[i] = c >> 2; bq[i] = c & 3;
        gB[i] = g_Wh + (size_t)brow[i] * KIN + bq[i] * 8;
        dB[i] = (uint32_t)(B_OFF + brow[i] * 80 + bq[i] * 16);
    }

    auto issue = [&](int s, int slot) {
        uint32_t st = sb + (uint32_t)slot * STG_BYTES;
        int kb = s * BK;
#pragma unroll
        for (int i = 0; i < 2; i++) cp_async16(st + dA[i], gA[i] + kb, szA[i]);
#pragma unroll
        for (int i = 0; i < 2; i++) cp_async16(st + dB[i], gB[i] + kb, 16);
    };

    float acc[2][8][4];
#pragma unroll
    for (int mi = 0; mi < 2; mi++)
#pragma unroll
        for (int ni = 0; ni < 8; ni++)
#pragma unroll
            for (int j = 0; j < 4; j++) acc[mi][ni][j] = 0.f;

    issue(0, 0); CP_COMMIT();
    issue(1, 1); CP_COMMIT();

    int cs = 0, is = 2;
#pragma unroll 1
    for (int ks = 0; ks < NKS; ks++) {
        CP_WAIT1();
        __syncthreads();
        if (ks + 2 < NKS) issue(ks + 2, is);
        CP_COMMIT();

        const float*    asb = (const float*)(smem + (size_t)cs * STG_BYTES);
        const uint32_t* bsb = (const uint32_t*)(smem + (size_t)cs * STG_BYTES + B_OFF);

#pragma unroll
        for (int kp = 0; kp < 2; kp++) {
            uint32_t afr[2][4];
#pragma unroll
            for (int mi = 0; mi < 2; mi++) {
                int m = wm * 32 + mi * 16 + r4;
                float2 f0 = *(const float2*)&asb[m * A_PITCH_F + kp * 16 + c4 * 2];
                float2 f1 = *(const float2*)&asb[(m + 8) * A_PITCH_F + kp * 16 + c4 * 2];
                float2 f2 = *(const float2*)&asb[m * A_PITCH_F + kp * 16 + c4 * 2 + 8];
                float2 f3 = *(const float2*)&asb[(m + 8) * A_PITCH_F + kp * 16 + c4 * 2 + 8];
                afr[mi][0] = f16x2(f0.x, f0.y);
                afr[mi][1] = f16x2(f1.x, f1.y);
                afr[mi][2] = f16x2(f2.x, f2.y);
                afr[mi][3] = f16x2(f3.x, f3.y);
            }
            uint32_t bfr[8][2];
#pragma unroll
            for (int ni = 0; ni < 8; ni++) {
                int n = wn * 64 + ni * 8 + r4;
                bfr[ni][0] = bsb[n * B_PITCH_W + kp * 8 + c4];
                bfr[ni][1] = bsb[n * B_PITCH_W + kp * 8 + c4 + 4];
            }
#pragma unroll
            for (int mi = 0; mi < 2; mi++)
#pragma unroll
                for (int ni = 0; ni < 8; ni++)
                    mma_f16(acc[mi][ni], afr[mi], bfr[ni]);
        }
        cs = (cs == 2) ? 0 : cs + 1;
        is = (is == 2) ? 0 : is + 1;
    }

    // ---- fused attn scalars (warp's 64 cols = one head = wn) ----
    const int head = wn;
    float avs[8][2], avd[8][2];
#pragma unroll
    for (int ni = 0; ni < 8; ni++) {
        int gn = head * 64 + ni * 8 + c4 * 2;
        avs[ni][0] = __ldg(&att_src[gn]);
        avs[ni][1] = __ldg(&att_src[gn + 1]);
        avd[ni][0] = __ldg(&att_dst[gn]);
        avd[ni][1] = __ldg(&att_dst[gn + 1]);
    }
#pragma unroll
    for (int mi = 0; mi < 2; mi++) {
        float ps0 = 0.f, ps1 = 0.f, pd0 = 0.f, pd1 = 0.f;
#pragma unroll
        for (int ni = 0; ni < 8; ni++) {
            ps0 += acc[mi][ni][0] * avs[ni][0] + acc[mi][ni][1] * avs[ni][1];
            ps1 += acc[mi][ni][2] * avs[ni][0] + acc[mi][ni][3] * avs[ni][1];
            pd0 += acc[mi][ni][0] * avd[ni][0] + acc[mi][ni][1] * avd[ni][1];
            pd1 += acc[mi][ni][2] * avd[ni][0] + acc[mi][ni][3] * avd[ni][1];
        }
#pragma unroll
        for (int o = 1; o <= 2; o <<= 1) {
            ps0 += __shfl_xor_sync(0xffffffffu, ps0, o);
            ps1 += __shfl_xor_sync(0xffffffffu, ps1, o);
            pd0 += __shfl_xor_sync(0xffffffffu, pd0, o);
            pd1 += __shfl_xor_sync(0xffffffffu, pd1, o);
        }
        if (c4 == 0) {
            int gmA = m0 + wm * 32 + mi * 16 + r4;
            int gmB = gmA + 8;
            if (gmA < NN) { g_asrc[gmA * HH + head] = ps0; g_adst[gmA * HH + head] = pd0; }
            if (gmB < NN) { g_asrc[gmB * HH + head] = ps1; g_adst[gmB * HH + head] = pd1; }
        }
    }

    // ---- write h as fp16 ----
#pragma unroll
    for (int mi = 0; mi < 2; mi++) {
#pragma unroll
        for (int ni = 0; ni < 8; ni++) {
            int gm = m0 + wm * 32 + mi * 16 + r4;
            int gn = wn * 64 + ni * 8 + (c4 << 1);
            if (gm < NN)
                *(__half2*)&g_h16[(size_t)gm * HC + gn] =
                    __float22half2_rn(make_float2(acc[mi][ni][0], acc[mi][ni][1]));
            if (gm + 8 < NN)
                *(__half2*)&g_h16[(size_t)(gm + 8) * HC + gn] =
                    __float22half2_rn(make_float2(acc[mi][ni][2], acc[mi][ni][3]));
        }
    }
}

// ---------------- 3) CSR build ----------------
__global__ void deg_init_kernel() {
    int i = blockIdx.x * blockDim.x + threadIdx.x;
    if (i < NN) g_deg[i] = 1;
}

__global__ void deg_count_kernel(const int* __restrict__ ei) {
    int e = blockIdx.x * blockDim.x + threadIdx.x;
    if (e < EE) atomicAdd(&g_deg[ei[EE + e]], 1);
}

__global__ __launch_bounds__(1024) void degsum_kernel() {
    __shared__ int ws[32];
    const int tid = threadIdx.x, lane = tid & 31, wid = tid >> 5;
    int base = blockIdx.x * SCAN_TILE + tid * 4;
    int s = 0;
    if (base + 3 < NN) {
        int4 v = *(const int4*)(g_deg + base);
        s = v.x + v.y + v.z + v.w;
    } else {
#pragma unroll
        for (int j = 0; j < 4; j++) if (base + j < NN) s += g_deg[base + j];
    }
#pragma unroll
    for (int o = 16; o > 0; o >>= 1) s += __shfl_xor_sync(0xffffffffu, s, o);
    if (lane == 0) ws[wid] = s;
    __syncthreads();
    if (wid == 0) {
        int t = ws[lane];
#pragma unroll
        for (int o = 16; o > 0; o >>= 1) t += __shfl_xor_sync(0xffffffffu, t, o);
        if (lane == 0) g_bsum[blockIdx.x] = t;
    }
}

__global__ void bscan_kernel() {
    int lane = threadIdx.x;
    int v = (lane < NBLK) ? g_bsum[lane] : 0;
    int x = v;
#pragma unroll
    for (int o = 1; o < 32; o <<= 1) {
        int y = __shfl_up_sync(0xffffffffu, x, o);
        if (lane >= o) x += y;
    }
    if (lane < NBLK) g_bbase[lane] = x - v;
    if (lane == 31) g_off[NN] = x;
}

__global__ __launch_bounds__(1024) void scan_write_kernel() {
    __shared__ int ws[32];
    const int tid = threadIdx.x, lane = tid & 31, wid = tid >> 5;
    int base = blockIdx.x * SCAN_TILE + tid * 4;
    int v[4] = {0, 0, 0, 0};
    if (base + 3 < NN) {
        int4 t = *(const int4*)(g_deg + base);
        v[0] = t.x; v[1] = t.y; v[2] = t.z; v[3] = t.w;
    } else {
#pragma unroll
        for (int j = 0; j < 4; j++) if (base + j < NN) v[j] = g_deg[base + j];
    }
    int tsum = v[0] + v[1] + v[2] + v[3];
    int x = tsum;
#pragma unroll
    for (int o = 1; o < 32; o <<= 1) {
        int y = __shfl_up_sync(0xffffffffu, x, o);
        if (lane >= o) x += y;
    }
    if (lane == 31) ws[wid] = x;
    __syncthreads();
    if (wid == 0) {
        int w = ws[lane];
        int xs = w;
#pragma unroll
        for (int o = 1; o < 32; o <<= 1) {
            int y = __shfl_up_sync(0xffffffffu, xs, o);
            if (lane >= o) xs += y;
        }
        ws[lane] = xs - w;
    }
    __syncthreads();
    int off = g_bbase[blockIdx.x] + ws[wid] + (x - tsum);
#pragma unroll
    for (int j = 0; j < 4; j++) {
        int i = base + j;
        if (i < NN) {
            g_off[i] = off;
            g_srcid[off] = i;
            g_cur[i] = off + 1;
        }
        off += v[j];
    }
}

__global__ void scatter_kernel(const int* __restrict__ ei) {
    int e = blockIdx.x * blockDim.x + threadIdx.x;
    if (e < EE) {
        int d = ei[EE + e];
        int p = atomicAdd(&g_cur[d], 1);
        g_srcid[p] = ei[e];
    }
}

// ---------------- 4) single-pass softmax-aggregation + epilogue ----------------
__device__ __forceinline__ float lrelu(float x) { return x >= 0.f ? x : NEG_SLOPE * x; }

__global__ __launch_bounds__(256) void smagg_kernel(const float* __restrict__ bias,
                                                    const float* __restrict__ prelu_a,
                                                    float* __restrict__ out) {
    int warp = (blockIdx.x * 256 + threadIdx.x) >> 5;
    int lane = threadIdx.x & 31;
    if (warp >= NN) return;
    const int node = warp;
    const int beg = g_off[node], end = g_off[node + 1];
    const int head = lane >> 3;

    float4 ad = *(const float4*)(g_adst + node * HH);
    float adh = (head == 0) ? ad.x : (head == 1) ? ad.y : (head == 2) ? ad.z : ad.w;

    float acc[8];
#pragma unroll
    for (int j = 0; j < 8; j++) acc[j] = 0.f;
    float esum = 0.f;

    const uint4* h4 = (const uint4*)g_h16;

    int i = beg;
    for (; i + 2 <= end; i += 2) {
        int sA = __ldg(&g_srcid[i]);
        int sB = __ldg(&g_srcid[i + 1]);
        float asA = __ldg(&g_asrc[sA * HH + head]);
        float asB = __ldg(&g_asrc[sB * HH + head]);
        uint4 hA = h4[(size_t)sA * 32 + lane];
        uint4 hB = h4[(size_t)sB * 32 + lane];
        float eA = __expf(lrelu(asA + adh));
        float eB = __expf(lrelu(asB + adh));
        esum += eA + eB;

        float2 p;
        p = __half22float2(*(__half2*)&hA.x); acc[0] = fmaf(eA, p.x, acc[0]); acc[1] = fmaf(eA, p.y, acc[1]);
        p = __half22float2(*(__half2*)&hA.y); acc[2] = fmaf(eA, p.x, acc[2]); acc[3] = fmaf(eA, p.y, acc[3]);
        p = __half22float2(*(__half2*)&hA.z); acc[4] = fmaf(eA, p.x, acc[4]); acc[5] = fmaf(eA, p.y, acc[5]);
        p = __half22float2(*(__half2*)&hA.w); acc[6] = fmaf(eA, p.x, acc[6]); acc[7] = fmaf(eA, p.y, acc[7]);
        p = __half22float2(*(__half2*)&hB.x); acc[0] = fmaf(eB, p.x, acc[0]); acc[1] = fmaf(eB, p.y, acc[1]);
        p = __half22float2(*(__half2*)&hB.y); acc[2] = fmaf(eB, p.x, acc[2]); acc[3] = fmaf(eB, p.y, acc[3]);
        p = __half22float2(*(__half2*)&hB.z); acc[4] = fmaf(eB, p.x, acc[4]); acc[5] = fmaf(eB, p.y, acc[5]);
        p = __half22float2(*(__half2*)&hB.w); acc[6] = fmaf(eB, p.x, acc[6]); acc[7] = fmaf(eB, p.y, acc[7]);
    }
    for (; i < end; i++) {
        int s = __ldg(&g_srcid[i]);
        float as = __ldg(&g_asrc[s * HH + head]);
        uint4 hv = h4[(size_t)s * 32 + lane];
        float e = __expf(lrelu(as + adh));
        esum += e;
        float2 p;
        p = __half22float2(*(__half2*)&hv.x); acc[0] = fmaf(e, p.x, acc[0]); acc[1] = fmaf(e, p.y, acc[1]);
        p = __half22float2(*(__half2*)&hv.y); acc[2] = fmaf(e, p.x, acc[2]); acc[3] = fmaf(e, p.y, acc[3]);
        p = __half22float2(*(__half2*)&hv.z); acc[4] = fmaf(e, p.x, acc[4]); acc[5] = fmaf(e, p.y, acc[5]);
        p = __half22float2(*(__half2*)&hv.w); acc[6] = fmaf(e, p.x, acc[6]); acc[7] = fmaf(e, p.y, acc[7]);
    }

    float inv = 1.f / (esum + 1e-16f);

    const float4* b4 = (const float4*)bias;
    float4 b0 = b4[lane * 2], b1 = b4[lane * 2 + 1];
    float pa = prelu_a[0];

    float o0 = fmaf(acc[0], inv, b0.x); o0 = o0 >= 0.f ? o0 : pa * o0;
    float o1 = fmaf(acc[1], inv, b0.y); o1 = o1 >= 0.f ? o1 : pa * o1;
    float o2 = fmaf(acc[2], inv, b0.z); o2 = o2 >= 0.f ? o2 : pa * o2;
    float o3 = fmaf(acc[3], inv, b0.w); o3 = o3 >= 0.f ? o3 : pa * o3;
    float o4 = fmaf(acc[4], inv, b1.x); o4 = o4 >= 0.f ? o4 : pa * o4;
    float o5 = fmaf(acc[5], inv, b1.y); o5 = o5 >= 0.f ? o5 : pa * o5;
    float o6 = fmaf(acc[6], inv, b1.z); o6 = o6 >= 0.f ? o6 : pa * o6;
    float o7 = fmaf(acc[7], inv, b1.w); o7 = o7 >= 0.f ? o7 : pa * o7;

    float4* out4 = (float4*)out;
    out4[node * (HC / 4) + lane * 2]     = make_float4(o0, o1, o2, o3);
    out4[node * (HC / 4) + lane * 2 + 1] = make_float4(o4, o5, o6, o7);
}

// ---------------- launch ----------------
extern "C" void kernel_launch(void* const* d_in, const int* in_sizes, int n_in,
                              void* d_out, int out_size) {
    const float* x       = (const float*)d_in[0];
    const int*   ei      = (const int*)d_in[1];
    const float* W       = (const float*)d_in[2];
    const float* att_src = (const float*)d_in[3];
    const float* att_dst = (const float*)d_in[4];
    const float* bias    = (const float*)d_in[5];
    const float* prelu_a = (const float*)d_in[6];
    float* out = (float*)d_out;

    static cudaStream_t s2;
    static cudaEvent_t evf, evj;
    static bool init_done = false;
    if (!init_done) {
        cudaStreamCreateWithFlags(&s2, cudaStreamNonBlocking);
        cudaEventCreateWithFlags(&evf, cudaEventDisableTiming);
        cudaEventCreateWithFlags(&evj, cudaEventDisableTiming);
        cudaFuncSetAttribute(mma_gemm_kernel, cudaFuncAttributeMaxDynamicSharedMemorySize, GEMM_SMEM);
        init_done = true;
    }

    // fork: CSR build on side stream (independent of W)
    cudaEventRecord(evf, 0);
    cudaStreamWaitEvent(s2, evf, 0);
    deg_init_kernel<<<(NN + 255) / 256, 256, 0, s2>>>();
    deg_count_kernel<<<(EE + 255) / 256, 256, 0, s2>>>(ei);
    degsum_kernel<<<NBLK, 1024, 0, s2>>>();
    bscan_kernel<<<1, 32, 0, s2>>>();
    scan_write_kernel<<<NBLK, 1024, 0, s2>>>();
    scatter_kernel<<<(EE + 255) / 256, 256, 0, s2>>>(ei);
    cudaEventRecord(evj, s2);

    // main stream: W^T then GEMM (full N=256 per block)
    wt_kernel<<<(KIN * HC + 255) / 256, 256>>>(W);
    mma_gemm_kernel<<<(NN + 127) / 128, 512, GEMM_SMEM>>>(x, att_src, att_dst);

    // join, then single-pass softmax+aggregate
    cudaStreamWaitEvent(0, evj, 0);
    smagg_kernel<<<(NN * 32 + 255) / 256, 256>>>(bias, prelu_a, out);
}

// round 13
// speedup vs baseline: 1.4352x; 1.4352x over previous
#include <cuda_runtime.h>
#include <cuda_fp16.h>
#include <cstdint>
#include <math.h>

#define NN   50000
#define EE   500000
#define KIN  512
#define HH   4
#define CC   64
#define HC   256
#define ET   (EE + NN)

#define NEG_SLOPE 0.2f

#define SCAN_TILE 4096
#define NBLK ((NN + SCAN_TILE - 1) / SCAN_TILE)   // 13

// ---------------- scratch (no allocations allowed) ----------------
__device__ __half g_Wh[HC * KIN];       // W transposed fp16 [N=256][K=512]
__device__ __half g_h16[NN * HC];       // projected features, fp16 copy for gather
__device__ float g_asrc[NN * HH];       // per-node src attn scores [N, H]
__device__ float g_adst[NN * HH];       // per-node dst attn scores [N, H]
__device__ int   g_deg[NN];             // in-degree (incl. self loop)
__device__ int   g_bsum[NBLK];          // per-scan-block degree sums
__device__ int   g_bbase[NBLK];         // exclusive prefix of block sums
__device__ int   g_off[NN + 1];         // CSR offsets
__device__ int   g_cur[NN];             // scatter cursors
__device__ int   g_srcid[ET];           // CSR: source node per incoming edge

__device__ __forceinline__ void mma_f16(float* c, const uint32_t* a, const uint32_t* b) {
    asm volatile(
        "mma.sync.aligned.m16n8k16.row.col.f32.f16.f16.f32 "
        "{%0,%1,%2,%3}, {%4,%5,%6,%7}, {%8,%9}, {%0,%1,%2,%3};"
        : "+f"(c[0]), "+f"(c[1]), "+f"(c[2]), "+f"(c[3])
        : "r"(a[0]), "r"(a[1]), "r"(a[2]), "r"(a[3]), "r"(b[0]), "r"(b[1]));
}

__device__ __forceinline__ uint32_t f16x2(float x, float y) {
    uint32_t d;
    asm("cvt.rn.f16x2.f32 %0, %1, %2;" : "=r"(d) : "f"(y), "f"(x));
    return d;
}

__device__ __forceinline__ uint32_t smem_u32(const void* p) {
    uint32_t a;
    asm("{ .reg .u64 t; cvta.to.shared.u64 t, %1; cvt.u32.u64 %0, t; }" : "=r"(a) : "l"(p));
    return a;
}
__device__ __forceinline__ void cp_async16(uint32_t dst, const void* src, int sz) {
    asm volatile("cp.async.cg.shared.global [%0], [%1], 16, %2;"
                 :: "r"(dst), "l"(src), "r"(sz) : "memory");
}
#define CP_COMMIT() asm volatile("cp.async.commit_group;" ::: "memory")
#define CP_WAIT1()  asm volatile("cp.async.wait_group 1;" ::: "memory")

// ---------------- 0) W transpose -> fp16 ----------------
__global__ void wt_kernel(const float* __restrict__ W) {
    int idx = blockIdx.x * blockDim.x + threadIdx.x;
    if (idx < KIN * HC) {
        int k = idx >> 8;
        int n = idx & 255;
        g_Wh[n * KIN + k] = __float2half_rn(W[idx]);
    }
}

// ---------------- 1) GEMM + fused attn scalars (R11 config: 128x128, 256 thr, 2 CTA/SM) ----------------
#define BK 32
#define NSTAGE 3
#define A_PITCH_F 40
#define B_PITCH_W 20
#define A_BYTES (128 * 160)
#define B_OFF   A_BYTES
#define STG_BYTES (A_BYTES + 128 * 80)   // 30720
#define GEMM_SMEM (NSTAGE * STG_BYTES)   // 92160
#define NKS (KIN / BK)   // 16

__global__ __launch_bounds__(256, 2) void mma_gemm_kernel(const float* __restrict__ x,
                                                          const float* __restrict__ att_src,
                                                          const float* __restrict__ att_dst) {
    extern __shared__ char smem[];
    const uint32_t sb = smem_u32(smem);

    const int tid  = threadIdx.x;
    const int lane = tid & 31;
    const int wid  = tid >> 5;
    const int wm   = wid & 3;
    const int wn   = wid >> 2;
    const int n0   = blockIdx.x * 128;
    const int m0   = blockIdx.y * 128;
    const int head = blockIdx.x * 2 + wn;
    const int r4   = lane >> 2;
    const int c4   = lane & 3;

    int arow[4], aq[4];
    const float* gA[4];
    int szA[4];
    uint32_t dA[4];
#pragma unroll
    for (int i = 0; i < 4; i++) {
        int c = i * 256 + tid;
        arow[i] = c >> 3; aq[i] = c & 7;
        gA[i] = x + (size_t)(m0 + arow[i]) * KIN + aq[i] * 4;
        szA[i] = (m0 + arow[i] < NN) ? 16 : 0;
        dA[i] = (uint32_t)(arow[i] * 160 + aq[i] * 16);
    }
    int brow[2], bq[2];
    const __half* gB[2];
    uint32_t dB[2];
#pragma unroll
    for (int i = 0; i < 2; i++) {
        int c = i * 256 + tid;
        brow[i] = c >> 2; bq[i] = c & 3;
        gB[i] = g_Wh + (size_t)(n0 + brow[i]) * KIN + bq[i] * 8;
        dB[i] = (uint32_t)(B_OFF + brow[i] * 80 + bq[i] * 16);
    }

    auto issue = [&](int s, int slot) {
        uint32_t st = sb + (uint32_t)slot * STG_BYTES;
        int kb = s * BK;
#pragma unroll
        for (int i = 0; i < 4; i++) cp_async16(st + dA[i], gA[i] + kb, szA[i]);
#pragma unroll
        for (int i = 0; i < 2; i++) cp_async16(st + dB[i], gB[i] + kb, 16);
    };

    float acc[2][8][4];
#pragma unroll
    for (int mi = 0; mi < 2; mi++)
#pragma unroll
        for (int ni = 0; ni < 8; ni++)
#pragma unroll
            for (int j = 0; j < 4; j++) acc[mi][ni][j] = 0.f;

    issue(0, 0); CP_COMMIT();
    issue(1, 1); CP_COMMIT();

    int cs = 0, is = 2;
#pragma unroll 1
    for (int ks = 0; ks < NKS; ks++) {
        CP_WAIT1();
        __syncthreads();
        if (ks + 2 < NKS) issue(ks + 2, is);
        CP_COMMIT();

        const float*    asb = (const float*)(smem + (size_t)cs * STG_BYTES);
        const uint32_t* bsb = (const uint32_t*)(smem + (size_t)cs * STG_BYTES + B_OFF);

#pragma unroll
        for (int kp = 0; kp < 2; kp++) {
            uint32_t afr[2][4];
#pragma unroll
            for (int mi = 0; mi < 2; mi++) {
                int m = wm * 32 + mi * 16 + r4;
                float2 f0 = *(const float2*)&asb[m * A_PITCH_F + kp * 16 + c4 * 2];
                float2 f1 = *(const float2*)&asb[(m + 8) * A_PITCH_F + kp * 16 + c4 * 2];
                float2 f2 = *(const float2*)&asb[m * A_PITCH_F + kp * 16 + c4 * 2 + 8];
                float2 f3 = *(const float2*)&asb[(m + 8) * A_PITCH_F + kp * 16 + c4 * 2 + 8];
                afr[mi][0] = f16x2(f0.x, f0.y);
                afr[mi][1] = f16x2(f1.x, f1.y);
                afr[mi][2] = f16x2(f2.x, f2.y);
                afr[mi][3] = f16x2(f3.x, f3.y);
            }
            uint32_t bfr[8][2];
#pragma unroll
            for (int ni = 0; ni < 8; ni++) {
                int n = wn * 64 + ni * 8 + r4;
                bfr[ni][0] = bsb[n * B_PITCH_W + kp * 8 + c4];
                bfr[ni][1] = bsb[n * B_PITCH_W + kp * 8 + c4 + 4];
            }
#pragma unroll
            for (int mi = 0; mi < 2; mi++)
#pragma unroll
                for (int ni = 0; ni < 8; ni++)
                    mma_f16(acc[mi][ni], afr[mi], bfr[ni]);
        }
        cs = (cs == 2) ? 0 : cs + 1;
        is = (is == 2) ? 0 : is + 1;
    }

    // ---- fused attn scalars ----
    float avs[8][2], avd[8][2];
#pragma unroll
    for (int ni = 0; ni < 8; ni++) {
        int gn = head * 64 + ni * 8 + c4 * 2;
        avs[ni][0] = __ldg(&att_src[gn]);
        avs[ni][1] = __ldg(&att_src[gn + 1]);
        avd[ni][0] = __ldg(&att_dst[gn]);
        avd[ni][1] = __ldg(&att_dst[gn + 1]);
    }
#pragma unroll
    for (int mi = 0; mi < 2; mi++) {
        float ps0 = 0.f, ps1 = 0.f, pd0 = 0.f, pd1 = 0.f;
#pragma unroll
        for (int ni = 0; ni < 8; ni++) {
            ps0 += acc[mi][ni][0] * avs[ni][0] + acc[mi][ni][1] * avs[ni][1];
            ps1 += acc[mi][ni][2] * avs[ni][0] + acc[mi][ni][3] * avs[ni][1];
            pd0 += acc[mi][ni][0] * avd[ni][0] + acc[mi][ni][1] * avd[ni][1];
            pd1 += acc[mi][ni][2] * avd[ni][0] + acc[mi][ni][3] * avd[ni][1];
        }
#pragma unroll
        for (int o = 1; o <= 2; o <<= 1) {
            ps0 += __shfl_xor_sync(0xffffffffu, ps0, o);
            ps1 += __shfl_xor_sync(0xffffffffu, ps1, o);
            pd0 += __shfl_xor_sync(0xffffffffu, pd0, o);
            pd1 += __shfl_xor_sync(0xffffffffu, pd1, o);
        }
        if (c4 == 0) {
            int gmA = m0 + wm * 32 + mi * 16 + r4;
            int gmB = gmA + 8;
            if (gmA < NN) { g_asrc[gmA * HH + head] = ps0; g_adst[gmA * HH + head] = pd0; }
            if (gmB < NN) { g_asrc[gmB * HH + head] = ps1; g_adst[gmB * HH + head] = pd1; }
        }
    }

    // ---- write h as fp16 ----
#pragma unroll
    for (int mi = 0; mi < 2; mi++) {
#pragma unroll
        for (int ni = 0; ni < 8; ni++) {
            int gm = m0 + wm * 32 + mi * 16 + r4;
            int gn = n0 + wn * 64 + ni * 8 + (c4 << 1);
            if (gm < NN)
                *(__half2*)&g_h16[(size_t)gm * HC + gn] =
                    __float22half2_rn(make_float2(acc[mi][ni][0], acc[mi][ni][1]));
            if (gm + 8 < NN)
                *(__half2*)&g_h16[(size_t)(gm + 8) * HC + gn] =
                    __float22half2_rn(make_float2(acc[mi][ni][2], acc[mi][ni][3]));
        }
    }
}

// ---------------- 3) CSR build ----------------
__global__ void deg_init_kernel() {
    int i = blockIdx.x * blockDim.x + threadIdx.x;
    if (i < NN) g_deg[i] = 1;
}

__global__ void deg_count_kernel(const int* __restrict__ ei) {
    int e = blockIdx.x * blockDim.x + threadIdx.x;
    if (e < EE) atomicAdd(&g_deg[ei[EE + e]], 1);
}

__global__ __launch_bounds__(1024) void degsum_kernel() {
    __shared__ int ws[32];
    const int tid = threadIdx.x, lane = tid & 31, wid = tid >> 5;
    int base = blockIdx.x * SCAN_TILE + tid * 4;
    int s = 0;
    if (base + 3 < NN) {
        int4 v = *(const int4*)(g_deg + base);
        s = v.x + v.y + v.z + v.w;
    } else {
#pragma unroll
        for (int j = 0; j < 4; j++) if (base + j < NN) s += g_deg[base + j];
    }
#pragma unroll
    for (int o = 16; o > 0; o >>= 1) s += __shfl_xor_sync(0xffffffffu, s, o);
    if (lane == 0) ws[wid] = s;
    __syncthreads();
    if (wid == 0) {
        int t = ws[lane];
#pragma unroll
        for (int o = 16; o > 0; o >>= 1) t += __shfl_xor_sync(0xffffffffu, t, o);
        if (lane == 0) g_bsum[blockIdx.x] = t;
    }
}

__global__ void bscan_kernel() {
    int lane = threadIdx.x;
    int v = (lane < NBLK) ? g_bsum[lane] : 0;
    int x = v;
#pragma unroll
    for (int o = 1; o < 32; o <<= 1) {
        int y = __shfl_up_sync(0xffffffffu, x, o);
        if (lane >= o) x += y;
    }
    if (lane < NBLK) g_bbase[lane] = x - v;
    if (lane == 31) g_off[NN] = x;
}

__global__ __launch_bounds__(1024) void scan_write_kernel() {
    __shared__ int ws[32];
    const int tid = threadIdx.x, lane = tid & 31, wid = tid >> 5;
    int base = blockIdx.x * SCAN_TILE + tid * 4;
    int v[4] = {0, 0, 0, 0};
    if (base + 3 < NN) {
        int4 t = *(const int4*)(g_deg + base);
        v[0] = t.x; v[1] = t.y; v[2] = t.z; v[3] = t.w;
    } else {
#pragma unroll
        for (int j = 0; j < 4; j++) if (base + j < NN) v[j] = g_deg[base + j];
    }
    int tsum = v[0] + v[1] + v[2] + v[3];
    int x = tsum;
#pragma unroll
    for (int o = 1; o < 32; o <<= 1) {
        int y = __shfl_up_sync(0xffffffffu, x, o);
        if (lane >= o) x += y;
    }
    if (lane == 31) ws[wid] = x;
    __syncthreads();
    if (wid == 0) {
        int w = ws[lane];
        int xs = w;
#pragma unroll
        for (int o = 1; o < 32; o <<= 1) {
            int y = __shfl_up_sync(0xffffffffu, xs, o);
            if (lane >= o) xs += y;
        }
        ws[lane] = xs - w;
    }
    __syncthreads();
    int off = g_bbase[blockIdx.x] + ws[wid] + (x - tsum);
#pragma unroll
    for (int j = 0; j < 4; j++) {
        int i = base + j;
        if (i < NN) {
            g_off[i] = off;
            g_srcid[off] = i;
            g_cur[i] = off + 1;
        }
        off += v[j];
    }
}

__global__ void scatter_kernel(const int* __restrict__ ei) {
    int e = blockIdx.x * blockDim.x + threadIdx.x;
    if (e < EE) {
        int d = ei[EE + e];
        int p = atomicAdd(&g_cur[d], 1);
        g_srcid[p] = ei[e];
    }
}

// ---------------- 4) single-pass softmax-aggregation + epilogue ----------------
__device__ __forceinline__ float lrelu(float x) { return x >= 0.f ? x : NEG_SLOPE * x; }

__global__ __launch_bounds__(512) void smagg_kernel(const float* __restrict__ bias,
                                                    const float* __restrict__ prelu_a,
                                                    float* __restrict__ out) {
    int warp = (blockIdx.x * 512 + threadIdx.x) >> 5;
    int lane = threadIdx.x & 31;
    if (warp >= NN) return;
    const int node = warp;
    const int beg = g_off[node], end = g_off[node + 1];
    const int head = lane >> 3;

    float4 ad = *(const float4*)(g_adst + node * HH);
    float adh = (head == 0) ? ad.x : (head == 1) ? ad.y : (head == 2) ? ad.z : ad.w;

    float acc[8];
#pragma unroll
    for (int j = 0; j < 8; j++) acc[j] = 0.f;
    float esum = 0.f;

    const uint4* h4 = (const uint4*)g_h16;

    int i = beg;
    for (; i + 2 <= end; i += 2) {
        int sA = __ldg(&g_srcid[i]);
        int sB = __ldg(&g_srcid[i + 1]);
        float asA = __ldg(&g_asrc[sA * HH + head]);
        float asB = __ldg(&g_asrc[sB * HH + head]);
        uint4 hA = h4[(size_t)sA * 32 + lane];
        uint4 hB = h4[(size_t)sB * 32 + lane];
        float eA = __expf(lrelu(asA + adh));
        float eB = __expf(lrelu(asB + adh));
        esum += eA + eB;

        float2 p;
        p = __half22float2(*(__half2*)&hA.x); acc[0] = fmaf(eA, p.x, acc[0]); acc[1] = fmaf(eA, p.y, acc[1]);
        p = __half22float2(*(__half2*)&hA.y); acc[2] = fmaf(eA, p.x, acc[2]); acc[3] = fmaf(eA, p.y, acc[3]);
        p = __half22float2(*(__half2*)&hA.z); acc[4] = fmaf(eA, p.x, acc[4]); acc[5] = fmaf(eA, p.y, acc[5]);
        p = __half22float2(*(__half2*)&hA.w); acc[6] = fmaf(eA, p.x, acc[6]); acc[7] = fmaf(eA, p.y, acc[7]);
        p = __half22float2(*(__half2*)&hB.x); acc[0] = fmaf(eB, p.x, acc[0]); acc[1] = fmaf(eB, p.y, acc[1]);
        p = __half22float2(*(__half2*)&hB.y); acc[2] = fmaf(eB, p.x, acc[2]); acc[3] = fmaf(eB, p.y, acc[3]);
        p = __half22float2(*(__half2*)&hB.z); acc[4] = fmaf(eB, p.x, acc[4]); acc[5] = fmaf(eB, p.y, acc[5]);
        p = __half22float2(*(__half2*)&hB.w); acc[6] = fmaf(eB, p.x, acc[6]); acc[7] = fmaf(eB, p.y, acc[7]);
    }
    for (; i < end; i++) {
        int s = __ldg(&g_srcid[i]);
        float as = __ldg(&g_asrc[s * HH + head]);
        uint4 hv = h4[(size_t)s * 32 + lane];
        float e = __expf(lrelu(as + adh));
        esum += e;
        float2 p;
        p = __half22float2(*(__half2*)&hv.x); acc[0] = fmaf(e, p.x, acc[0]); acc[1] = fmaf(e, p.y, acc[1]);
        p = __half22float2(*(__half2*)&hv.y); acc[2] = fmaf(e, p.x, acc[2]); acc[3] = fmaf(e, p.y, acc[3]);
        p = __half22float2(*(__half2*)&hv.z); acc[4] = fmaf(e, p.x, acc[4]); acc[5] = fmaf(e, p.y, acc[5]);
        p = __half22float2(*(__half2*)&hv.w); acc[6] = fmaf(e, p.x, acc[6]); acc[7] = fmaf(e, p.y, acc[7]);
    }

    float inv = 1.f / (esum + 1e-16f);

    const float4* b4 = (const float4*)bias;
    float4 b0 = b4[lane * 2], b1 = b4[lane * 2 + 1];
    float pa = prelu_a[0];

    float o0 = fmaf(acc[0], inv, b0.x); o0 = o0 >= 0.f ? o0 : pa * o0;
    float o1 = fmaf(acc[1], inv, b0.y); o1 = o1 >= 0.f ? o1 : pa * o1;
    float o2 = fmaf(acc[2], inv, b0.z); o2 = o2 >= 0.f ? o2 : pa * o2;
    float o3 = fmaf(acc[3], inv, b0.w); o3 = o3 >= 0.f ? o3 : pa * o3;
    float o4 = fmaf(acc[4], inv, b1.x); o4 = o4 >= 0.f ? o4 : pa * o4;
    float o5 = fmaf(acc[5], inv, b1.y); o5 = o5 >= 0.f ? o5 : pa * o5;
    float o6 = fmaf(acc[6], inv, b1.z); o6 = o6 >= 0.f ? o6 : pa * o6;
    float o7 = fmaf(acc[7], inv, b1.w); o7 = o7 >= 0.f ? o7 : pa * o7;

    float4* out4 = (float4*)out;
    out4[node * (HC / 4) + lane * 2]     = make_float4(o0, o1, o2, o3);
    out4[node * (HC / 4) + lane * 2 + 1] = make_float4(o4, o5, o6, o7);
}

// ---------------- launch ----------------
extern "C" void kernel_launch(void* const* d_in, const int* in_sizes, int n_in,
                              void* d_out, int out_size) {
    const float* x       = (const float*)d_in[0];
    const int*   ei      = (const int*)d_in[1];
    const float* W       = (const float*)d_in[2];
    const float* att_src = (const float*)d_in[3];
    const float* att_dst = (const float*)d_in[4];
    const float* bias    = (const float*)d_in[5];
    const float* prelu_a = (const float*)d_in[6];
    float* out = (float*)d_out;

    static cudaStream_t s2;
    static cudaEvent_t evf, evj;
    static bool init_done = false;
    if (!init_done) {
        cudaStreamCreateWithFlags(&s2, cudaStreamNonBlocking);
        cudaEventCreateWithFlags(&evf, cudaEventDisableTiming);
        cudaEventCreateWithFlags(&evj, cudaEventDisableTiming);
        cudaFuncSetAttribute(mma_gemm_kernel, cudaFuncAttributeMaxDynamicSharedMemorySize, GEMM_SMEM);
        init_done = true;
    }

    // fork: CSR build on side stream
    cudaEventRecord(evf, 0);
    cudaStreamWaitEvent(s2, evf, 0);
    deg_init_kernel<<<(NN + 511) / 512, 512, 0, s2>>>();
    deg_count_kernel<<<(EE + 255) / 256, 256, 0, s2>>>(ei);
    degsum_kernel<<<NBLK, 1024, 0, s2>>>();
    bscan_kernel<<<1, 32, 0, s2>>>();
    scan_write_kernel<<<NBLK, 1024, 0, s2>>>();
    scatter_kernel<<<(EE + 255) / 256, 256, 0, s2>>>(ei);
    cudaEventRecord(evj, s2);

    // main stream: W^T then GEMM (R11 config)
    wt_kernel<<<(KIN * HC + 255) / 256, 256>>>(W);
    dim3 ggrid(2, (NN + 127) / 128);
    mma_gemm_kernel<<<ggrid, 256, GEMM_SMEM>>>(x, att_src, att_dst);

    // join, then single-pass softmax+aggregate
    cudaStreamWaitEvent(0, evj, 0);
    smagg_kernel<<<(NN * 32 + 511) / 512, 512>>>(bias, prelu_a, out);
}

// round 14
// speedup vs baseline: 1.4602x; 1.0174x over previous
#include <cuda_runtime.h>
#include <cuda_fp16.h>
#include <cstdint>
#include <math.h>

#define NN   50000
#define EE   500000
#define KIN  512
#define HH   4
#define CC   64
#define HC   256
#define ET   (EE + NN)

#define NEG_SLOPE 0.2f

#define SCAN_TILE 4096
#define NBLK ((NN + SCAN_TILE - 1) / SCAN_TILE)   // 13

// ---------------- scratch (no allocations allowed) ----------------
__device__ __half g_Wh[HC * KIN];       // W transposed fp16 [N=256][K=512]
__device__ __half g_h16[NN * HC];       // projected features, fp16 copy for gather
__device__ float g_asrc[NN * HH];       // per-node src attn scores [N, H]
__device__ float g_adst[NN * HH];       // per-node dst attn scores [N, H]
__device__ int   g_deg[NN];             // in-degree (incl. self loop)
__device__ int   g_bsum[NBLK];          // per-scan-block degree sums
__device__ int   g_bbase[NBLK];         // exclusive prefix of block sums
__device__ int   g_off[NN + 1];         // CSR offsets
__device__ int   g_cur[NN];             // scatter cursors
__device__ int   g_srcid[ET];           // CSR: source node per incoming edge

__device__ __forceinline__ void mma_f16(float* c, const uint32_t* a, const uint32_t* b) {
    asm volatile(
        "mma.sync.aligned.m16n8k16.row.col.f32.f16.f16.f32 "
        "{%0,%1,%2,%3}, {%4,%5,%6,%7}, {%8,%9}, {%0,%1,%2,%3};"
        : "+f"(c[0]), "+f"(c[1]), "+f"(c[2]), "+f"(c[3])
        : "r"(a[0]), "r"(a[1]), "r"(a[2]), "r"(a[3]), "r"(b[0]), "r"(b[1]));
}

__device__ __forceinline__ uint32_t f16x2(float x, float y) {
    uint32_t d;
    asm("cvt.rn.f16x2.f32 %0, %1, %2;" : "=r"(d) : "f"(y), "f"(x));
    return d;
}

__device__ __forceinline__ uint32_t smem_u32(const void* p) {
    uint32_t a;
    asm("{ .reg .u64 t; cvta.to.shared.u64 t, %1; cvt.u32.u64 %0, t; }" : "=r"(a) : "l"(p));
    return a;
}
__device__ __forceinline__ void cp_async16(uint32_t dst, const void* src, int sz) {
    asm volatile("cp.async.cg.shared.global [%0], [%1], 16, %2;"
                 :: "r"(dst), "l"(src), "r"(sz) : "memory");
}
#define CP_COMMIT() asm volatile("cp.async.commit_group;" ::: "memory")
#define CP_WAIT1()  asm volatile("cp.async.wait_group 1;" ::: "memory")

// ---------------- 0) W transpose -> fp16 ----------------
__global__ void wt_kernel(const float* __restrict__ W) {
    int idx = blockIdx.x * blockDim.x + threadIdx.x;
    if (idx < KIN * HC) {
        int k = idx >> 8;
        int n = idx & 255;
        g_Wh[n * KIN + k] = __float2half_rn(W[idx]);
    }
}

// ---------------- 1) GEMM + fused attn scalars (128x128, 256 thr, 2 CTA/SM) ----------------
#define BK 32
#define NSTAGE 3
#define A_PITCH_F 40
#define B_PITCH_W 20
#define A_BYTES (128 * 160)
#define B_OFF   A_BYTES
#define STG_BYTES (A_BYTES + 128 * 80)   // 30720
#define GEMM_SMEM (NSTAGE * STG_BYTES)   // 92160
#define NKS (KIN / BK)   // 16

__global__ __launch_bounds__(256, 2) void mma_gemm_kernel(const float* __restrict__ x,
                                                          const float* __restrict__ att_src,
                                                          const float* __restrict__ att_dst) {
    extern __shared__ char smem[];
    const uint32_t sb = smem_u32(smem);

    const int tid  = threadIdx.x;
    const int lane = tid & 31;
    const int wid  = tid >> 5;
    const int wm   = wid & 3;
    const int wn   = wid >> 2;
    const int n0   = blockIdx.x * 128;
    const int m0   = blockIdx.y * 128;
    const int head = blockIdx.x * 2 + wn;
    const int r4   = lane >> 2;
    const int c4   = lane & 3;

    int arow[4], aq[4];
    const float* gA[4];
    int szA[4];
    uint32_t dA[4];
#pragma unroll
    for (int i = 0; i < 4; i++) {
        int c = i * 256 + tid;
        arow[i] = c >> 3; aq[i] = c & 7;
        gA[i] = x + (size_t)(m0 + arow[i]) * KIN + aq[i] * 4;
        szA[i] = (m0 + arow[i] < NN) ? 16 : 0;
        dA[i] = (uint32_t)(arow[i] * 160 + aq[i] * 16);
    }
    int brow[2], bq[2];
    const __half* gB[2];
    uint32_t dB[2];
#pragma unroll
    for (int i = 0; i < 2; i++) {
        int c = i * 256 + tid;
        brow[i] = c >> 2; bq[i] = c & 3;
        gB[i] = g_Wh + (size_t)(n0 + brow[i]) * KIN + bq[i] * 8;
        dB[i] = (uint32_t)(B_OFF + brow[i] * 80 + bq[i] * 16);
    }

    auto issue = [&](int s, int slot) {
        uint32_t st = sb + (uint32_t)slot * STG_BYTES;
        int kb = s * BK;
#pragma unroll
        for (int i = 0; i < 4; i++) cp_async16(st + dA[i], gA[i] + kb, szA[i]);
#pragma unroll
        for (int i = 0; i < 2; i++) cp_async16(st + dB[i], gB[i] + kb, 16);
    };

    float acc[2][8][4];
#pragma unroll
    for (int mi = 0; mi < 2; mi++)
#pragma unroll
        for (int ni = 0; ni < 8; ni++)
#pragma unroll
            for (int j = 0; j < 4; j++) acc[mi][ni][j] = 0.f;

    issue(0, 0); CP_COMMIT();
    issue(1, 1); CP_COMMIT();

    int cs = 0, is = 2;
#pragma unroll 1
    for (int ks = 0; ks < NKS; ks++) {
        CP_WAIT1();
        __syncthreads();
        if (ks + 2 < NKS) issue(ks + 2, is);
        CP_COMMIT();

        const float*    asb = (const float*)(smem + (size_t)cs * STG_BYTES);
        const uint32_t* bsb = (const uint32_t*)(smem + (size_t)cs * STG_BYTES + B_OFF);

#pragma unroll
        for (int kp = 0; kp < 2; kp++) {
            uint32_t afr[2][4];
#pragma unroll
            for (int mi = 0; mi < 2; mi++) {
                int m = wm * 32 + mi * 16 + r4;
                float2 f0 = *(const float2*)&asb[m * A_PITCH_F + kp * 16 + c4 * 2];
                float2 f1 = *(const float2*)&asb[(m + 8) * A_PITCH_F + kp * 16 + c4 * 2];
                float2 f2 = *(const float2*)&asb[m * A_PITCH_F + kp * 16 + c4 * 2 + 8];
                float2 f3 = *(const float2*)&asb[(m + 8) * A_PITCH_F + kp * 16 + c4 * 2 + 8];
                afr[mi][0] = f16x2(f0.x, f0.y);
                afr[mi][1] = f16x2(f1.x, f1.y);
                afr[mi][2] = f16x2(f2.x, f2.y);
                afr[mi][3] = f16x2(f3.x, f3.y);
            }
            uint32_t bfr[8][2];
#pragma unroll
            for (int ni = 0; ni < 8; ni++) {
                int n = wn * 64 + ni * 8 + r4;
                bfr[ni][0] = bsb[n * B_PITCH_W + kp * 8 + c4];
                bfr[ni][1] = bsb[n * B_PITCH_W + kp * 8 + c4 + 4];
            }
#pragma unroll
            for (int mi = 0; mi < 2; mi++)
#pragma unroll
                for (int ni = 0; ni < 8; ni++)
                    mma_f16(acc[mi][ni], afr[mi], bfr[ni]);
        }
        cs = (cs == 2) ? 0 : cs + 1;
        is = (is == 2) ? 0 : is + 1;
    }

    // ---- fused attn scalars ----
    float avs[8][2], avd[8][2];
#pragma unroll
    for (int ni = 0; ni < 8; ni++) {
        int gn = head * 64 + ni * 8 + c4 * 2;
        avs[ni][0] = __ldg(&att_src[gn]);
        avs[ni][1] = __ldg(&att_src[gn + 1]);
        avd[ni][0] = __ldg(&att_dst[gn]);
        avd[ni][1] = __ldg(&att_dst[gn + 1]);
    }
#pragma unroll
    for (int mi = 0; mi < 2; mi++) {
        float ps0 = 0.f, ps1 = 0.f, pd0 = 0.f, pd1 = 0.f;
#pragma unroll
        for (int ni = 0; ni < 8; ni++) {
            ps0 += acc[mi][ni][0] * avs[ni][0] + acc[mi][ni][1] * avs[ni][1];
            ps1 += acc[mi][ni][2] * avs[ni][0] + acc[mi][ni][3] * avs[ni][1];
            pd0 += acc[mi][ni][0] * avd[ni][0] + acc[mi][ni][1] * avd[ni][1];
            pd1 += acc[mi][ni][2] * avd[ni][0] + acc[mi][ni][3] * avd[ni][1];
        }
#pragma unroll
        for (int o = 1; o <= 2; o <<= 1) {
            ps0 += __shfl_xor_sync(0xffffffffu, ps0, o);
            ps1 += __shfl_xor_sync(0xffffffffu, ps1, o);
            pd0 += __shfl_xor_sync(0xffffffffu, pd0, o);
            pd1 += __shfl_xor_sync(0xffffffffu, pd1, o);
        }
        if (c4 == 0) {
            int gmA = m0 + wm * 32 + mi * 16 + r4;
            int gmB = gmA + 8;
            if (gmA < NN) { g_asrc[gmA * HH + head] = ps0; g_adst[gmA * HH + head] = pd0; }
            if (gmB < NN) { g_asrc[gmB * HH + head] = ps1; g_adst[gmB * HH + head] = pd1; }
        }
    }

    // ---- write h as fp16 ----
#pragma unroll
    for (int mi = 0; mi < 2; mi++) {
#pragma unroll
        for (int ni = 0; ni < 8; ni++) {
            int gm = m0 + wm * 32 + mi * 16 + r4;
            int gn = n0 + wn * 64 + ni * 8 + (c4 << 1);
            if (gm < NN)
                *(__half2*)&g_h16[(size_t)gm * HC + gn] =
                    __float22half2_rn(make_float2(acc[mi][ni][0], acc[mi][ni][1]));
            if (gm + 8 < NN)
                *(__half2*)&g_h16[(size_t)(gm + 8) * HC + gn] =
                    __float22half2_rn(make_float2(acc[mi][ni][2], acc[mi][ni][3]));
        }
    }
}

// ---------------- 3) CSR build ----------------
__global__ void deg_init_kernel() {
    int i = blockIdx.x * blockDim.x + threadIdx.x;
    if (i < NN) g_deg[i] = 1;
}

__global__ void deg_count_kernel(const int* __restrict__ ei) {
    int e = blockIdx.x * blockDim.x + threadIdx.x;
    if (e < EE) atomicAdd(&g_deg[ei[EE + e]], 1);
}

__global__ __launch_bounds__(1024) void degsum_kernel() {
    __shared__ int ws[32];
    const int tid = threadIdx.x, lane = tid & 31, wid = tid >> 5;
    int base = blockIdx.x * SCAN_TILE + tid * 4;
    int s = 0;
    if (base + 3 < NN) {
        int4 v = *(const int4*)(g_deg + base);
        s = v.x + v.y + v.z + v.w;
    } else {
#pragma unroll
        for (int j = 0; j < 4; j++) if (base + j < NN) s += g_deg[base + j];
    }
#pragma unroll
    for (int o = 16; o > 0; o >>= 1) s += __shfl_xor_sync(0xffffffffu, s, o);
    if (lane == 0) ws[wid] = s;
    __syncthreads();
    if (wid == 0) {
        int t = ws[lane];
#pragma unroll
        for (int o = 16; o > 0; o >>= 1) t += __shfl_xor_sync(0xffffffffu, t, o);
        if (lane == 0) g_bsum[blockIdx.x] = t;
    }
}

__global__ void bscan_kernel() {
    int lane = threadIdx.x;
    int v = (lane < NBLK) ? g_bsum[lane] : 0;
    int x = v;
#pragma unroll
    for (int o = 1; o < 32; o <<= 1) {
        int y = __shfl_up_sync(0xffffffffu, x, o);
        if (lane >= o) x += y;
    }
    if (lane < NBLK) g_bbase[lane] = x - v;
    if (lane == 31) g_off[NN] = x;
}

__global__ __launch_bounds__(1024) void scan_write_kernel() {
    __shared__ int ws[32];
    const int tid = threadIdx.x, lane = tid & 31, wid = tid >> 5;
    int base = blockIdx.x * SCAN_TILE + tid * 4;
    int v[4] = {0, 0, 0, 0};
    if (base + 3 < NN) {
        int4 t = *(const int4*)(g_deg + base);
        v[0] = t.x; v[1] = t.y; v[2] = t.z; v[3] = t.w;
    } else {
#pragma unroll
        for (int j = 0; j < 4; j++) if (base + j < NN) v[j] = g_deg[base + j];
    }
    int tsum = v[0] + v[1] + v[2] + v[3];
    int x = tsum;
#pragma unroll
    for (int o = 1; o < 32; o <<= 1) {
        int y = __shfl_up_sync(0xffffffffu, x, o);
        if (lane >= o) x += y;
    }
    if (lane == 31) ws[wid] = x;
    __syncthreads();
    if (wid == 0) {
        int w = ws[lane];
        int xs = w;
#pragma unroll
        for (int o = 1; o < 32; o <<= 1) {
            int y = __shfl_up_sync(0xffffffffu, xs, o);
            if (lane >= o) xs += y;
        }
        ws[lane] = xs - w;
    }
    __syncthreads();
    int off = g_bbase[blockIdx.x] + ws[wid] + (x - tsum);
#pragma unroll
    for (int j = 0; j < 4; j++) {
        int i = base + j;
        if (i < NN) {
            g_off[i] = off;
            g_srcid[off] = i;
            g_cur[i] = off + 1;
        }
        off += v[j];
    }
}

__global__ void scatter_kernel(const int* __restrict__ ei) {
    int e = blockIdx.x * blockDim.x + threadIdx.x;
    if (e < EE) {
        int d = ei[EE + e];
        int p = atomicAdd(&g_cur[d], 1);
        g_srcid[p] = ei[e];
    }
}

// ---------------- 4) single-pass softmax-aggregation + epilogue ----------------
__device__ __forceinline__ float lrelu(float x) { return x >= 0.f ? x : NEG_SLOPE * x; }

__global__ __launch_bounds__(256) void smagg_kernel(const float* __restrict__ bias,
                                                    const float* __restrict__ prelu_a,
                                                    float* __restrict__ out) {
    int warp = (blockIdx.x * 256 + threadIdx.x) >> 5;
    int lane = threadIdx.x & 31;
    if (warp >= NN) return;
    const int node = warp;
    const int beg = g_off[node], end = g_off[node + 1];
    const int head = lane >> 3;

    float4 ad = *(const float4*)(g_adst + node * HH);
    float adh = (head == 0) ? ad.x : (head == 1) ? ad.y : (head == 2) ? ad.z : ad.w;

    float acc[8];
#pragma unroll
    for (int j = 0; j < 8; j++) acc[j] = 0.f;
    float esum = 0.f;

    const uint4* h4 = (const uint4*)g_h16;

    int i = beg;
    for (; i + 2 <= end; i += 2) {
        int sA = __ldg(&g_srcid[i]);
        int sB = __ldg(&g_srcid[i + 1]);
        float asA = __ldg(&g_asrc[sA * HH + head]);
        float asB = __ldg(&g_asrc[sB * HH + head]);
        uint4 hA = h4[(size_t)sA * 32 + lane];
        uint4 hB = h4[(size_t)sB * 32 + lane];
        float eA = __expf(lrelu(asA + adh));
        float eB = __expf(lrelu(asB + adh));
        esum += eA + eB;

        float2 p;
        p = __half22float2(*(__half2*)&hA.x); acc[0] = fmaf(eA, p.x, acc[0]); acc[1] = fmaf(eA, p.y, acc[1]);
        p = __half22float2(*(__half2*)&hA.y); acc[2] = fmaf(eA, p.x, acc[2]); acc[3] = fmaf(eA, p.y, acc[3]);
        p = __half22float2(*(__half2*)&hA.z); acc[4] = fmaf(eA, p.x, acc[4]); acc[5] = fmaf(eA, p.y, acc[5]);
        p = __half22float2(*(__half2*)&hA.w); acc[6] = fmaf(eA, p.x, acc[6]); acc[7] = fmaf(eA, p.y, acc[7]);
        p = __half22float2(*(__half2*)&hB.x); acc[0] = fmaf(eB, p.x, acc[0]); acc[1] = fmaf(eB, p.y, acc[1]);
        p = __half22float2(*(__half2*)&hB.y); acc[2] = fmaf(eB, p.x, acc[2]); acc[3] = fmaf(eB, p.y, acc[3]);
        p = __half22float2(*(__half2*)&hB.z); acc[4] = fmaf(eB, p.x, acc[4]); acc[5] = fmaf(eB, p.y, acc[5]);
        p = __half22float2(*(__half2*)&hB.w); acc[6] = fmaf(eB, p.x, acc[6]); acc[7] = fmaf(eB, p.y, acc[7]);
    }
    for (; i < end; i++) {
        int s = __ldg(&g_srcid[i]);
        float as = __ldg(&g_asrc[s * HH + head]);
        uint4 hv = h4[(size_t)s * 32 + lane];
        float e = __expf(lrelu(as + adh));
        esum += e;
        float2 p;
        p = __half22float2(*(__half2*)&hv.x); acc[0] = fmaf(e, p.x, acc[0]); acc[1] = fmaf(e, p.y, acc[1]);
        p = __half22float2(*(__half2*)&hv.y); acc[2] = fmaf(e, p.x, acc[2]); acc[3] = fmaf(e, p.y, acc[3]);
        p = __half22float2(*(__half2*)&hv.z); acc[4] = fmaf(e, p.x, acc[4]); acc[5] = fmaf(e, p.y, acc[5]);
        p = __half22float2(*(__half2*)&hv.w); acc[6] = fmaf(e, p.x, acc[6]); acc[7] = fmaf(e, p.y, acc[7]);
    }

    float inv = 1.f / (esum + 1e-16f);

    const float4* b4 = (const float4*)bias;
    float4 b0 = b4[lane * 2], b1 = b4[lane * 2 + 1];
    float pa = prelu_a[0];

    float o0 = fmaf(acc[0], inv, b0.x); o0 = o0 >= 0.f ? o0 : pa * o0;
    float o1 = fmaf(acc[1], inv, b0.y); o1 = o1 >= 0.f ? o1 : pa * o1;
    float o2 = fmaf(acc[2], inv, b0.z); o2 = o2 >= 0.f ? o2 : pa * o2;
    float o3 = fmaf(acc[3], inv, b0.w); o3 = o3 >= 0.f ? o3 : pa * o3;
    float o4 = fmaf(acc[4], inv, b1.x); o4 = o4 >= 0.f ? o4 : pa * o4;
    float o5 = fmaf(acc[5], inv, b1.y); o5 = o5 >= 0.f ? o5 : pa * o5;
    float o6 = fmaf(acc[6], inv, b1.z); o6 = o6 >= 0.f ? o6 : pa * o6;
    float o7 = fmaf(acc[7], inv, b1.w); o7 = o7 >= 0.f ? o7 : pa * o7;

    float4* out4 = (float4*)out;
    out4[node * (HC / 4) + lane * 2]     = make_float4(o0, o1, o2, o3);
    out4[node * (HC / 4) + lane * 2 + 1] = make_float4(o4, o5, o6, o7);
}

// ---------------- launch ----------------
extern "C" void kernel_launch(void* const* d_in, const int* in_sizes, int n_in,
                              void* d_out, int out_size) {
    const float* x       = (const float*)d_in[0];
    const int*   ei      = (const int*)d_in[1];
    const float* W       = (const float*)d_in[2];
    const float* att_src = (const float*)d_in[3];
    const float* att_dst = (const float*)d_in[4];
    const float* bias    = (const float*)d_in[5];
    const float* prelu_a = (const float*)d_in[6];
    float* out = (float*)d_out;

    static cudaStream_t s2;
    static cudaEvent_t evf, evj;
    static bool init_done = false;
    if (!init_done) {
        cudaStreamCreateWithFlags(&s2, cudaStreamNonBlocking);
        cudaEventCreateWithFlags(&evf, cudaEventDisableTiming);
        cudaEventCreateWithFlags(&evj, cudaEventDisableTiming);
        cudaFuncSetAttribute(mma_gemm_kernel, cudaFuncAttributeMaxDynamicSharedMemorySize, GEMM_SMEM);
        init_done = true;
    }

    // fork: CSR build on side stream (independent of W)
    cudaEventRecord(evf, 0);
    cudaStreamWaitEvent(s2, evf, 0);
    deg_init_kernel<<<(NN + 255) / 256, 256, 0, s2>>>();
    deg_count_kernel<<<(EE + 255) / 256, 256, 0, s2>>>(ei);
    degsum_kernel<<<NBLK, 1024, 0, s2>>>();
    bscan_kernel<<<1, 32, 0, s2>>>();
    scan_write_kernel<<<NBLK, 1024, 0, s2>>>();
    scatter_kernel<<<(EE + 255) / 256, 256, 0, s2>>>(ei);
    cudaEventRecord(evj, s2);

    // main stream: W^T then GEMM
    wt_kernel<<<(KIN * HC + 255) / 256, 256>>>(W);
    dim3 ggrid(2, (NN + 127) / 128);
    mma_gemm_kernel<<<ggrid, 256, GEMM_SMEM>>>(x, att_src, att_dst);

    // join, then single-pass softmax+aggregate
    cudaStreamWaitEvent(0, evj, 0);
    smagg_kernel<<<(NN * 32 + 255) / 256, 256>>>(bias, prelu_a, out);
}

// round 15
// speedup vs baseline: 1.4720x; 1.0081x over previous
#include <cuda_runtime.h>
#include <cuda_fp16.h>
#include <cstdint>
#include <math.h>

#define NN   50000
#define EE   500000
#define KIN  512
#define HH   4
#define CC   64
#define HC   256
#define ET   (EE + NN)

#define NEG_SLOPE 0.2f

#define SCAN_TILE 4096
#define NBLK ((NN + SCAN_TILE - 1) / SCAN_TILE)   // 13

// ---------------- scratch (no allocations allowed) ----------------
__device__ __half g_Wh[HC * KIN];       // W transposed fp16 [N=256][K=512]
__device__ __half g_h16[NN * HC];       // projected features, fp16 copy for gather
__device__ float g_asrc[NN * HH];       // per-node src attn scores [N, H]
__device__ float g_adst[NN * HH];       // per-node dst attn scores [N, H]
__device__ int   g_deg[NN];             // in-degree (incl. self loop)
__device__ int   g_bsum[NBLK];          // per-scan-block degree sums
__device__ int   g_bbase[NBLK];         // exclusive prefix of block sums
__device__ int   g_off[NN + 1];         // CSR offsets
__device__ int   g_cur[NN];             // scatter cursors
__device__ int   g_srcid[ET];           // CSR: source node per incoming edge

__device__ __forceinline__ void mma_f16(float* c, const uint32_t* a, const uint32_t* b) {
    asm volatile(
        "mma.sync.aligned.m16n8k16.row.col.f32.f16.f16.f32 "
        "{%0,%1,%2,%3}, {%4,%5,%6,%7}, {%8,%9}, {%0,%1,%2,%3};"
        : "+f"(c[0]), "+f"(c[1]), "+f"(c[2]), "+f"(c[3])
        : "r"(a[0]), "r"(a[1]), "r"(a[2]), "r"(a[3]), "r"(b[0]), "r"(b[1]));
}

__device__ __forceinline__ uint32_t f16x2(float x, float y) {
    uint32_t d;
    asm("cvt.rn.f16x2.f32 %0, %1, %2;" : "=r"(d) : "f"(y), "f"(x));
    return d;
}

__device__ __forceinline__ uint32_t smem_u32(const void* p) {
    uint32_t a;
    asm("{ .reg .u64 t; cvta.to.shared.u64 t, %1; cvt.u32.u64 %0, t; }" : "=r"(a) : "l"(p));
    return a;
}
__device__ __forceinline__ void cp_async16(uint32_t dst, const void* src, int sz) {
    asm volatile("cp.async.cg.shared.global [%0], [%1], 16, %2;"
                 :: "r"(dst), "l"(src), "r"(sz) : "memory");
}
#define CP_COMMIT() asm volatile("cp.async.commit_group;" ::: "memory")
#define CP_WAIT1()  asm volatile("cp.async.wait_group 1;" ::: "memory")

// ---------------- 0) W transpose -> fp16 ----------------
__global__ void wt_kernel(const float* __restrict__ W) {
    int idx = blockIdx.x * blockDim.x + threadIdx.x;
    if (idx < KIN * HC) {
        int k = idx >> 8;
        int n = idx & 255;
        g_Wh[n * KIN + k] = __float2half_rn(W[idx]);
    }
}

// ---------------- 1) GEMM + fused attn scalars (128x128, 256 thr, 2 CTA/SM) ----------------
#define BK 32
#define NSTAGE 3
#define A_PITCH_F 40
#define B_PITCH_W 20
#define A_BYTES (128 * 160)
#define B_OFF   A_BYTES
#define STG_BYTES (A_BYTES + 128 * 80)   // 30720
#define GEMM_SMEM (NSTAGE * STG_BYTES)   // 92160
#define NKS (KIN / BK)   // 16

__global__ __launch_bounds__(256, 2) void mma_gemm_kernel(const float* __restrict__ x,
                                                          const float* __restrict__ att_src,
                                                          const float* __restrict__ att_dst) {
    extern __shared__ char smem[];
    const uint32_t sb = smem_u32(smem);

    const int tid  = threadIdx.x;
    const int lane = tid & 31;
    const int wid  = tid >> 5;
    const int wm   = wid & 3;
    const int wn   = wid >> 2;
    const int n0   = blockIdx.x * 128;
    const int m0   = blockIdx.y * 128;
    const int head = blockIdx.x * 2 + wn;
    const int r4   = lane >> 2;
    const int c4   = lane & 3;

    int arow[4], aq[4];
    const float* gA[4];
    int szA[4];
    uint32_t dA[4];
#pragma unroll
    for (int i = 0; i < 4; i++) {
        int c = i * 256 + tid;
        arow[i] = c >> 3; aq[i] = c & 7;
        gA[i] = x + (size_t)(m0 + arow[i]) * KIN + aq[i] * 4;
        szA[i] = (m0 + arow[i] < NN) ? 16 : 0;
        dA[i] = (uint32_t)(arow[i] * 160 + aq[i] * 16);
    }
    int brow[2], bq[2];
    const __half* gB[2];
    uint32_t dB[2];
#pragma unroll
    for (int i = 0; i < 2; i++) {
        int c = i * 256 + tid;
        brow[i] = c >> 2; bq[i] = c & 3;
        gB[i] = g_Wh + (size_t)(n0 + brow[i]) * KIN + bq[i] * 8;
        dB[i] = (uint32_t)(B_OFF + brow[i] * 80 + bq[i] * 16);
    }

    auto issue = [&](int s, int slot) {
        uint32_t st = sb + (uint32_t)slot * STG_BYTES;
        int kb = s * BK;
#pragma unroll
        for (int i = 0; i < 4; i++) cp_async16(st + dA[i], gA[i] + kb, szA[i]);
#pragma unroll
        for (int i = 0; i < 2; i++) cp_async16(st + dB[i], gB[i] + kb, 16);
    };

    float acc[2][8][4];
#pragma unroll
    for (int mi = 0; mi < 2; mi++)
#pragma unroll
        for (int ni = 0; ni < 8; ni++)
#pragma unroll
            for (int j = 0; j < 4; j++) acc[mi][ni][j] = 0.f;

    issue(0, 0); CP_COMMIT();
    issue(1, 1); CP_COMMIT();

    int cs = 0, is = 2;
#pragma unroll 1
    for (int ks = 0; ks < NKS; ks++) {
        CP_WAIT1();
        __syncthreads();
        if (ks + 2 < NKS) issue(ks + 2, is);
        CP_COMMIT();

        const float*    asb = (const float*)(smem + (size_t)cs * STG_BYTES);
        const uint32_t* bsb = (const uint32_t*)(smem + (size_t)cs * STG_BYTES + B_OFF);

#pragma unroll
        for (int kp = 0; kp < 2; kp++) {
            uint32_t afr[2][4];
#pragma unroll
            for (int mi = 0; mi < 2; mi++) {
                int m = wm * 32 + mi * 16 + r4;
                float2 f0 = *(const float2*)&asb[m * A_PITCH_F + kp * 16 + c4 * 2];
                float2 f1 = *(const float2*)&asb[(m + 8) * A_PITCH_F + kp * 16 + c4 * 2];
                float2 f2 = *(const float2*)&asb[m * A_PITCH_F + kp * 16 + c4 * 2 + 8];
                float2 f3 = *(const float2*)&asb[(m + 8) * A_PITCH_F + kp * 16 + c4 * 2 + 8];
                afr[mi][0] = f16x2(f0.x, f0.y);
                afr[mi][1] = f16x2(f1.x, f1.y);
                afr[mi][2] = f16x2(f2.x, f2.y);
                afr[mi][3] = f16x2(f3.x, f3.y);
            }
            uint32_t bfr[8][2];
#pragma unroll
            for (int ni = 0; ni < 8; ni++) {
                int n = wn * 64 + ni * 8 + r4;
                bfr[ni][0] = bsb[n * B_PITCH_W + kp * 8 + c4];
                bfr[ni][1] = bsb[n * B_PITCH_W + kp * 8 + c4 + 4];
            }
#pragma unroll
            for (int mi = 0; mi < 2; mi++)
#pragma unroll
                for (int ni = 0; ni < 8; ni++)
                    mma_f16(acc[mi][ni], afr[mi], bfr[ni]);
        }
        cs = (cs == 2) ? 0 : cs + 1;
        is = (is == 2) ? 0 : is + 1;
    }

    // ---- fused attn scalars ----
    float avs[8][2], avd[8][2];
#pragma unroll
    for (int ni = 0; ni < 8; ni++) {
        int gn = head * 64 + ni * 8 + c4 * 2;
        avs[ni][0] = __ldg(&att_src[gn]);
        avs[ni][1] = __ldg(&att_src[gn + 1]);
        avd[ni][0] = __ldg(&att_dst[gn]);
        avd[ni][1] = __ldg(&att_dst[gn + 1]);
    }
#pragma unroll
    for (int mi = 0; mi < 2; mi++) {
        float ps0 = 0.f, ps1 = 0.f, pd0 = 0.f, pd1 = 0.f;
#pragma unroll
        for (int ni = 0; ni < 8; ni++) {
            ps0 += acc[mi][ni][0] * avs[ni][0] + acc[mi][ni][1] * avs[ni][1];
            ps1 += acc[mi][ni][2] * avs[ni][0] + acc[mi][ni][3] * avs[ni][1];
            pd0 += acc[mi][ni][0] * avd[ni][0] + acc[mi][ni][1] * avd[ni][1];
            pd1 += acc[mi][ni][2] * avd[ni][0] + acc[mi][ni][3] * avd[ni][1];
        }
#pragma unroll
        for (int o = 1; o <= 2; o <<= 1) {
            ps0 += __shfl_xor_sync(0xffffffffu, ps0, o);
            ps1 += __shfl_xor_sync(0xffffffffu, ps1, o);
            pd0 += __shfl_xor_sync(0xffffffffu, pd0, o);
            pd1 += __shfl_xor_sync(0xffffffffu, pd1, o);
        }
        if (c4 == 0) {
            int gmA = m0 + wm * 32 + mi * 16 + r4;
            int gmB = gmA + 8;
            if (gmA < NN) { g_asrc[gmA * HH + head] = ps0; g_adst[gmA * HH + head] = pd0; }
            if (gmB < NN) { g_asrc[gmB * HH + head] = ps1; g_adst[gmB * HH + head] = pd1; }
        }
    }

    // ---- write h as fp16 ----
#pragma unroll
    for (int mi = 0; mi < 2; mi++) {
#pragma unroll
        for (int ni = 0; ni < 8; ni++) {
            int gm = m0 + wm * 32 + mi * 16 + r4;
            int gn = n0 + wn * 64 + ni * 8 + (c4 << 1);
            if (gm < NN)
                *(__half2*)&g_h16[(size_t)gm * HC + gn] =
                    __float22half2_rn(make_float2(acc[mi][ni][0], acc[mi][ni][1]));
            if (gm + 8 < NN)
                *(__half2*)&g_h16[(size_t)(gm + 8) * HC + gn] =
                    __float22half2_rn(make_float2(acc[mi][ni][2], acc[mi][ni][3]));
        }
    }
}

// ---------------- 3) CSR build ----------------
__global__ void deg_init_kernel() {
    int i = blockIdx.x * blockDim.x + threadIdx.x;
    if (i < NN) g_deg[i] = 1;
}

__global__ void deg_count_kernel(const int* __restrict__ ei) {
    int e = blockIdx.x * blockDim.x + threadIdx.x;
    if (e < EE) atomicAdd(&g_deg[ei[EE + e]], 1);
}

__global__ __launch_bounds__(1024) void degsum_kernel() {
    __shared__ int ws[32];
    const int tid = threadIdx.x, lane = tid & 31, wid = tid >> 5;
    int base = blockIdx.x * SCAN_TILE + tid * 4;
    int s = 0;
    if (base + 3 < NN) {
        int4 v = *(const int4*)(g_deg + base);
        s = v.x + v.y + v.z + v.w;
    } else {
#pragma unroll
        for (int j = 0; j < 4; j++) if (base + j < NN) s += g_deg[base + j];
    }
#pragma unroll
    for (int o = 16; o > 0; o >>= 1) s += __shfl_xor_sync(0xffffffffu, s, o);
    if (lane == 0) ws[wid] = s;
    __syncthreads();
    if (wid == 0) {
        int t = ws[lane];
#pragma unroll
        for (int o = 16; o > 0; o >>= 1) t += __shfl_xor_sync(0xffffffffu, t, o);
        if (lane == 0) g_bsum[blockIdx.x] = t;
    }
}

__global__ void bscan_kernel() {
    int lane = threadIdx.x;
    int v = (lane < NBLK) ? g_bsum[lane] : 0;
    int x = v;
#pragma unroll
    for (int o = 1; o < 32; o <<= 1) {
        int y = __shfl_up_sync(0xffffffffu, x, o);
        if (lane >= o) x += y;
    }
    if (lane < NBLK) g_bbase[lane] = x - v;
    if (lane == 31) g_off[NN] = x;
}

__global__ __launch_bounds__(1024) void scan_write_kernel() {
    __shared__ int ws[32];
    const int tid = threadIdx.x, lane = tid & 31, wid = tid >> 5;
    int base = blockIdx.x * SCAN_TILE + tid * 4;
    int v[4] = {0, 0, 0, 0};
    if (base + 3 < NN) {
        int4 t = *(const int4*)(g_deg + base);
        v[0] = t.x; v[1] = t.y; v[2] = t.z; v[3] = t.w;
    } else {
#pragma unroll
        for (int j = 0; j < 4; j++) if (base + j < NN) v[j] = g_deg[base + j];
    }
    int tsum = v[0] + v[1] + v[2] + v[3];
    int x = tsum;
#pragma unroll
    for (int o = 1; o < 32; o <<= 1) {
        int y = __shfl_up_sync(0xffffffffu, x, o);
        if (lane >= o) x += y;
    }
    if (lane == 31) ws[wid] = x;
    __syncthreads();
    if (wid == 0) {
        int w = ws[lane];
        int xs = w;
#pragma unroll
        for (int o = 1; o < 32; o <<= 1) {
            int y = __shfl_up_sync(0xffffffffu, xs, o);
            if (lane >= o) xs += y;
        }
        ws[lane] = xs - w;
    }
    __syncthreads();
    int off = g_bbase[blockIdx.x] + ws[wid] + (x - tsum);
#pragma unroll
    for (int j = 0; j < 4; j++) {
        int i = base + j;
        if (i < NN) {
            g_off[i] = off;
            g_srcid[off] = i;
            g_cur[i] = off + 1;
        }
        off += v[j];
    }
}

__global__ void scatter_kernel(const int* __restrict__ ei) {
    int e = blockIdx.x * blockDim.x + threadIdx.x;
    if (e < EE) {
        int d = ei[EE + e];
        int p = atomicAdd(&g_cur[d], 1);
        g_srcid[p] = ei[e];
    }
}

// ---------------- 4) single-pass softmax-aggregation + epilogue ----------------
__device__ __forceinline__ float lrelu(float x) { return x >= 0.f ? x : NEG_SLOPE * x; }

__global__ __launch_bounds__(256) void smagg_kernel(const float* __restrict__ bias,
                                                    const float* __restrict__ prelu_a,
                                                    float* __restrict__ out) {
    int warp = (blockIdx.x * 256 + threadIdx.x) >> 5;
    int lane = threadIdx.x & 31;
    if (warp >= NN) return;
    const int node = warp;
    const int beg = g_off[node], end = g_off[node + 1];
    const int head = lane >> 3;

    float4 ad = *(const float4*)(g_adst + node * HH);
    float adh = (head == 0) ? ad.x : (head == 1) ? ad.y : (head == 2) ? ad.z : ad.w;

    float acc[8];
#pragma unroll
    for (int j = 0; j < 8; j++) acc[j] = 0.f;
    float esum = 0.f;

    const uint4* h4 = (const uint4*)g_h16;

    int i = beg;
    for (; i + 2 <= end; i += 2) {
        int sA = __ldg(&g_srcid[i]);
        int sB = __ldg(&g_srcid[i + 1]);
        float asA = __ldg(&g_asrc[sA * HH + head]);
        float asB = __ldg(&g_asrc[sB * HH + head]);
        uint4 hA = h4[(size_t)sA * 32 + lane];
        uint4 hB = h4[(size_t)sB * 32 + lane];
        float eA = __expf(lrelu(asA + adh));
        float eB = __expf(lrelu(asB + adh));
        esum += eA + eB;

        float2 p;
        p = __half22float2(*(__half2*)&hA.x); acc[0] = fmaf(eA, p.x, acc[0]); acc[1] = fmaf(eA, p.y, acc[1]);
        p = __half22float2(*(__half2*)&hA.y); acc[2] = fmaf(eA, p.x, acc[2]); acc[3] = fmaf(eA, p.y, acc[3]);
        p = __half22float2(*(__half2*)&hA.z); acc[4] = fmaf(eA, p.x, acc[4]); acc[5] = fmaf(eA, p.y, acc[5]);
        p = __half22float2(*(__half2*)&hA.w); acc[6] = fmaf(eA, p.x, acc[6]); acc[7] = fmaf(eA, p.y, acc[7]);
        p = __half22float2(*(__half2*)&hB.x); acc[0] = fmaf(eB, p.x, acc[0]); acc[1] = fmaf(eB, p.y, acc[1]);
        p = __half22float2(*(__half2*)&hB.y); acc[2] = fmaf(eB, p.x, acc[2]); acc[3] = fmaf(eB, p.y, acc[3]);
        p = __half22float2(*(__half2*)&hB.z); acc[4] = fmaf(eB, p.x, acc[4]); acc[5] = fmaf(eB, p.y, acc[5]);
        p = __half22float2(*(__half2*)&hB.w); acc[6] = fmaf(eB, p.x, acc[6]); acc[7] = fmaf(eB, p.y, acc[7]);
    }
    for (; i < end; i++) {
        int s = __ldg(&g_srcid[i]);
        float as = __ldg(&g_asrc[s * HH + head]);
        uint4 hv = h4[(size_t)s * 32 + lane];
        float e = __expf(lrelu(as + adh));
        esum += e;
        float2 p;
        p = __half22float2(*(__half2*)&hv.x); acc[0] = fmaf(e, p.x, acc[0]); acc[1] = fmaf(e, p.y, acc[1]);
        p = __half22float2(*(__half2*)&hv.y); acc[2] = fmaf(e, p.x, acc[2]); acc[3] = fmaf(e, p.y, acc[3]);
        p = __half22float2(*(__half2*)&hv.z); acc[4] = fmaf(e, p.x, acc[4]); acc[5] = fmaf(e, p.y, acc[5]);
        p = __half22float2(*(__half2*)&hv.w); acc[6] = fmaf(e, p.x, acc[6]); acc[7] = fmaf(e, p.y, acc[7]);
    }

    float inv = 1.f / (esum + 1e-16f);

    const float4* b4 = (const float4*)bias;
    float4 b0 = b4[lane * 2], b1 = b4[lane * 2 + 1];
    float pa = prelu_a[0];

    float o0 = fmaf(acc[0], inv, b0.x); o0 = o0 >= 0.f ? o0 : pa * o0;
    float o1 = fmaf(acc[1], inv, b0.y); o1 = o1 >= 0.f ? o1 : pa * o1;
    float o2 = fmaf(acc[2], inv, b0.z); o2 = o2 >= 0.f ? o2 : pa * o2;
    float o3 = fmaf(acc[3], inv, b0.w); o3 = o3 >= 0.f ? o3 : pa * o3;
    float o4 = fmaf(acc[4], inv, b1.x); o4 = o4 >= 0.f ? o4 : pa * o4;
    float o5 = fmaf(acc[5], inv, b1.y); o5 = o5 >= 0.f ? o5 : pa * o5;
    float o6 = fmaf(acc[6], inv, b1.z); o6 = o6 >= 0.f ? o6 : pa * o6;
    float o7 = fmaf(acc[7], inv, b1.w); o7 = o7 >= 0.f ? o7 : pa * o7;

    // evict-first streaming stores: keep g_h16 resident in L2 for the gather
    float4* out4 = (float4*)out;
    __stcs(&out4[node * (HC / 4) + lane * 2],     make_float4(o0, o1, o2, o3));
    __stcs(&out4[node * (HC / 4) + lane * 2 + 1], make_float4(o4, o5, o6, o7));
}

// ---------------- launch ----------------
extern "C" void kernel_launch(void* const* d_in, const int* in_sizes, int n_in,
                              void* d_out, int out_size) {
    const float* x       = (const float*)d_in[0];
    const int*   ei      = (const int*)d_in[1];
    const float* W       = (const float*)d_in[2];
    const float* att_src = (const float*)d_in[3];
    const float* att_dst = (const float*)d_in[4];
    const float* bias    = (const float*)d_in[5];
    const float* prelu_a = (const float*)d_in[6];
    float* out = (float*)d_out;

    static cudaStream_t s2;
    static cudaEvent_t evf, evj;
    static bool init_done = false;
    if (!init_done) {
        cudaStreamCreateWithFlags(&s2, cudaStreamNonBlocking);
        cudaEventCreateWithFlags(&evf, cudaEventDisableTiming);
        cudaEventCreateWithFlags(&evj, cudaEventDisableTiming);
        cudaFuncSetAttribute(mma_gemm_kernel, cudaFuncAttributeMaxDynamicSharedMemorySize, GEMM_SMEM);
        init_done = true;
    }

    // fork: CSR build on side stream (independent of W)
    cudaEventRecord(evf, 0);
    cudaStreamWaitEvent(s2, evf, 0);
    deg_init_kernel<<<(NN + 255) / 256, 256, 0, s2>>>();
    deg_count_kernel<<<(EE + 255) / 256, 256, 0, s2>>>(ei);
    degsum_kernel<<<NBLK, 1024, 0, s2>>>();
    bscan_kernel<<<1, 32, 0, s2>>>();
    scan_write_kernel<<<NBLK, 1024, 0, s2>>>();
    scatter_kernel<<<(EE + 255) / 256, 256, 0, s2>>>(ei);
    cudaEventRecord(evj, s2);

    // main stream: W^T then GEMM
    wt_kernel<<<(KIN * HC + 255) / 256, 256>>>(W);
    dim3 ggrid(2, (NN + 127) / 128);
    mma_gemm_kernel<<<ggrid, 256, GEMM_SMEM>>>(x, att_src, att_dst);

    // join, then single-pass softmax+aggregate
    cudaStreamWaitEvent(0, evj, 0);
    smagg_kernel<<<(NN * 32 + 255) / 256, 256>>>(bias, prelu_a, out);
}

// round 16
// speedup vs baseline: 1.5278x; 1.0379x over previous
#include <cuda_runtime.h>
#include <cuda_fp16.h>
#include <cstdint>
#include <math.h>

#define NN   50000
#define EE   500000
#define KIN  512
#define HH   4
#define CC   64
#define HC   256
#define ET   (EE + NN)

#define NEG_SLOPE 0.2f

#define SCAN_TILE 4096
#define NBLK ((NN + SCAN_TILE - 1) / SCAN_TILE)   // 13

// ---------------- scratch (no allocations allowed) ----------------
__device__ __half g_Wh[HC * KIN];       // W transposed fp16 [N=256][K=512]
__device__ __half g_h16[NN * HC];       // projected features, fp16 copy for gather
__device__ float g_asrc[NN * HH];       // per-node src attn scores [N, H]
__device__ float g_adst[NN * HH];       // per-node dst attn scores [N, H]
__device__ int   g_deg[NN];             // in-degree (incl. self loop)
__device__ int   g_bsum[NBLK];          // per-scan-block degree sums
__device__ int   g_bbase[NBLK];         // exclusive prefix of block sums
__device__ int   g_off[NN + 1];         // CSR offsets
__device__ int   g_cur[NN];             // scatter cursors
__device__ int   g_srcid[ET];           // CSR: source node per incoming edge

__device__ __forceinline__ void mma_f16(float* c, const uint32_t* a, const uint32_t* b) {
    asm volatile(
        "mma.sync.aligned.m16n8k16.row.col.f32.f16.f16.f32 "
        "{%0,%1,%2,%3}, {%4,%5,%6,%7}, {%8,%9}, {%0,%1,%2,%3};"
        : "+f"(c[0]), "+f"(c[1]), "+f"(c[2]), "+f"(c[3])
        : "r"(a[0]), "r"(a[1]), "r"(a[2]), "r"(a[3]), "r"(b[0]), "r"(b[1]));
}

__device__ __forceinline__ uint32_t f16x2(float x, float y) {
    uint32_t d;
    asm("cvt.rn.f16x2.f32 %0, %1, %2;" : "=r"(d) : "f"(y), "f"(x));
    return d;
}

__device__ __forceinline__ uint32_t smem_u32(const void* p) {
    uint32_t a;
    asm("{ .reg .u64 t; cvta.to.shared.u64 t, %1; cvt.u32.u64 %0, t; }" : "=r"(a) : "l"(p));
    return a;
}
__device__ __forceinline__ void cp_async16(uint32_t dst, const void* src, int sz) {
    asm volatile("cp.async.cg.shared.global [%0], [%1], 16, %2;"
                 :: "r"(dst), "l"(src), "r"(sz) : "memory");
}
#define CP_COMMIT() asm volatile("cp.async.commit_group;" ::: "memory")
#define CP_WAIT1()  asm volatile("cp.async.wait_group 1;" ::: "memory")

// ---------------- 0) W transpose -> fp16 ----------------
__global__ void wt_kernel(const float* __restrict__ W) {
    int idx = blockIdx.x * blockDim.x + threadIdx.x;
    if (idx < KIN * HC) {
        int k = idx >> 8;
        int n = idx & 255;
        g_Wh[n * KIN + k] = __float2half_rn(W[idx]);
    }
}

// ---------------- 1) GEMM + fused attn scalars (128x128, 256 thr, 2 CTA/SM) ----------------
#define BK 32
#define NSTAGE 3
#define A_PITCH_F 40
#define B_PITCH_W 20
#define A_BYTES (128 * 160)
#define B_OFF   A_BYTES
#define STG_BYTES (A_BYTES + 128 * 80)   // 30720
#define GEMM_SMEM (NSTAGE * STG_BYTES)   // 92160
#define NKS (KIN / BK)   // 16

__global__ __launch_bounds__(256, 2) void mma_gemm_kernel(const float* __restrict__ x,
                                                          const float* __restrict__ att_src,
                                                          const float* __restrict__ att_dst) {
    extern __shared__ char smem[];
    const uint32_t sb = smem_u32(smem);

    const int tid  = threadIdx.x;
    const int lane = tid & 31;
    const int wid  = tid >> 5;
    const int wm   = wid & 3;
    const int wn   = wid >> 2;
    const int n0   = blockIdx.x * 128;
    const int m0   = blockIdx.y * 128;
    const int head = blockIdx.x * 2 + wn;
    const int r4   = lane >> 2;
    const int c4   = lane & 3;

    int arow[4], aq[4];
    const float* gA[4];
    int szA[4];
    uint32_t dA[4];
#pragma unroll
    for (int i = 0; i < 4; i++) {
        int c = i * 256 + tid;
        arow[i] = c >> 3; aq[i] = c & 7;
        gA[i] = x + (size_t)(m0 + arow[i]) * KIN + aq[i] * 4;
        szA[i] = (m0 + arow[i] < NN) ? 16 : 0;
        dA[i] = (uint32_t)(arow[i] * 160 + aq[i] * 16);
    }
    int brow[2], bq[2];
    const __half* gB[2];
    uint32_t dB[2];
#pragma unroll
    for (int i = 0; i < 2; i++) {
        int c = i * 256 + tid;
        brow[i] = c >> 2; bq[i] = c & 3;
        gB[i] = g_Wh + (size_t)(n0 + brow[i]) * KIN + bq[i] * 8;
        dB[i] = (uint32_t)(B_OFF + brow[i] * 80 + bq[i] * 16);
    }

    auto issue = [&](int s, int slot) {
        uint32_t st = sb + (uint32_t)slot * STG_BYTES;
        int kb = s * BK;
#pragma unroll
        for (int i = 0; i < 4; i++) cp_async16(st + dA[i], gA[i] + kb, szA[i]);
#pragma unroll
        for (int i = 0; i < 2; i++) cp_async16(st + dB[i], gB[i] + kb, 16);
    };

    float acc[2][8][4];
#pragma unroll
    for (int mi = 0; mi < 2; mi++)
#pragma unroll
        for (int ni = 0; ni < 8; ni++)
#pragma unroll
            for (int j = 0; j < 4; j++) acc[mi][ni][j] = 0.f;

    issue(0, 0); CP_COMMIT();
    issue(1, 1); CP_COMMIT();

    int cs = 0, is = 2;
#pragma unroll 1
    for (int ks = 0; ks < NKS; ks++) {
        CP_WAIT1();
        __syncthreads();
        if (ks + 2 < NKS) issue(ks + 2, is);
        CP_COMMIT();

        const float*    asb = (const float*)(smem + (size_t)cs * STG_BYTES);
        const uint32_t* bsb = (const uint32_t*)(smem + (size_t)cs * STG_BYTES + B_OFF);

#pragma unroll
        for (int kp = 0; kp < 2; kp++) {
            uint32_t afr[2][4];
#pragma unroll
            for (int mi = 0; mi < 2; mi++) {
                int m = wm * 32 + mi * 16 + r4;
                float2 f0 = *(const float2*)&asb[m * A_PITCH_F + kp * 16 + c4 * 2];
                float2 f1 = *(const float2*)&asb[(m + 8) * A_PITCH_F + kp * 16 + c4 * 2];
                float2 f2 = *(const float2*)&asb[m * A_PITCH_F + kp * 16 + c4 * 2 + 8];
                float2 f3 = *(const float2*)&asb[(m + 8) * A_PITCH_F + kp * 16 + c4 * 2 + 8];
                afr[mi][0] = f16x2(f0.x, f0.y);
                afr[mi][1] = f16x2(f1.x, f1.y);
                afr[mi][2] = f16x2(f2.x, f2.y);
                afr[mi][3] = f16x2(f3.x, f3.y);
            }
            uint32_t bfr[8][2];
#pragma unroll
            for (int ni = 0; ni < 8; ni++) {
                int n = wn * 64 + ni * 8 + r4;
                bfr[ni][0] = bsb[n * B_PITCH_W + kp * 8 + c4];
                bfr[ni][1] = bsb[n * B_PITCH_W + kp * 8 + c4 + 4];
            }
#pragma unroll
            for (int mi = 0; mi < 2; mi++)
#pragma unroll
                for (int ni = 0; ni < 8; ni++)
                    mma_f16(acc[mi][ni], afr[mi], bfr[ni]);
        }
        cs = (cs == 2) ? 0 : cs + 1;
        is = (is == 2) ? 0 : is + 1;
    }

    // ---- fused attn scalars ----
    float avs[8][2], avd[8][2];
#pragma unroll
    for (int ni = 0; ni < 8; ni++) {
        int gn = head * 64 + ni * 8 + c4 * 2;
        avs[ni][0] = __ldg(&att_src[gn]);
        avs[ni][1] = __ldg(&att_src[gn + 1]);
        avd[ni][0] = __ldg(&att_dst[gn]);
        avd[ni][1] = __ldg(&att_dst[gn + 1]);
    }
#pragma unroll
    for (int mi = 0; mi < 2; mi++) {
        float ps0 = 0.f, ps1 = 0.f, pd0 = 0.f, pd1 = 0.f;
#pragma unroll
        for (int ni = 0; ni < 8; ni++) {
            ps0 += acc[mi][ni][0] * avs[ni][0] + acc[mi][ni][1] * avs[ni][1];
            ps1 += acc[mi][ni][2] * avs[ni][0] + acc[mi][ni][3] * avs[ni][1];
            pd0 += acc[mi][ni][0] * avd[ni][0] + acc[mi][ni][1] * avd[ni][1];
            pd1 += acc[mi][ni][2] * avd[ni][0] + acc[mi][ni][3] * avd[ni][1];
        }
#pragma unroll
        for (int o = 1; o <= 2; o <<= 1) {
            ps0 += __shfl_xor_sync(0xffffffffu, ps0, o);
            ps1 += __shfl_xor_sync(0xffffffffu, ps1, o);
            pd0 += __shfl_xor_sync(0xffffffffu, pd0, o);
            pd1 += __shfl_xor_sync(0xffffffffu, pd1, o);
        }
        if (c4 == 0) {
            int gmA = m0 + wm * 32 + mi * 16 + r4;
            int gmB = gmA + 8;
            if (gmA < NN) { g_asrc[gmA * HH + head] = ps0; g_adst[gmA * HH + head] = pd0; }
            if (gmB < NN) { g_asrc[gmB * HH + head] = ps1; g_adst[gmB * HH + head] = pd1; }
        }
    }

    // ---- write h as fp16 ----
#pragma unroll
    for (int mi = 0; mi < 2; mi++) {
#pragma unroll
        for (int ni = 0; ni < 8; ni++) {
            int gm = m0 + wm * 32 + mi * 16 + r4;
            int gn = n0 + wn * 64 + ni * 8 + (c4 << 1);
            if (gm < NN)
                *(__half2*)&g_h16[(size_t)gm * HC + gn] =
                    __float22half2_rn(make_float2(acc[mi][ni][0], acc[mi][ni][1]));
            if (gm + 8 < NN)
                *(__half2*)&g_h16[(size_t)(gm + 8) * HC + gn] =
                    __float22half2_rn(make_float2(acc[mi][ni][2], acc[mi][ni][3]));
        }
    }
}

// ---------------- 3) CSR build ----------------
__global__ void deg_init_kernel() {
    int i = blockIdx.x * blockDim.x + threadIdx.x;
    if (i < NN) g_deg[i] = 1;
}

__global__ void deg_count_kernel(const int* __restrict__ ei) {
    int e = blockIdx.x * blockDim.x + threadIdx.x;
    if (e < EE) atomicAdd(&g_deg[ei[EE + e]], 1);
}

__global__ __launch_bounds__(1024) void degsum_kernel() {
    __shared__ int ws[32];
    const int tid = threadIdx.x, lane = tid & 31, wid = tid >> 5;
    int base = blockIdx.x * SCAN_TILE + tid * 4;
    int s = 0;
    if (base + 3 < NN) {
        int4 v = *(const int4*)(g_deg + base);
        s = v.x + v.y + v.z + v.w;
    } else {
#pragma unroll
        for (int j = 0; j < 4; j++) if (base + j < NN) s += g_deg[base + j];
    }
#pragma unroll
    for (int o = 16; o > 0; o >>= 1) s += __shfl_xor_sync(0xffffffffu, s, o);
    if (lane == 0) ws[wid] = s;
    __syncthreads();
    if (wid == 0) {
        int t = ws[lane];
#pragma unroll
        for (int o = 16; o > 0; o >>= 1) t += __shfl_xor_sync(0xffffffffu, t, o);
        if (lane == 0) g_bsum[blockIdx.x] = t;
    }
}

__global__ void bscan_kernel() {
    int lane = threadIdx.x;
    int v = (lane < NBLK) ? g_bsum[lane] : 0;
    int x = v;
#pragma unroll
    for (int o = 1; o < 32; o <<= 1) {
        int y = __shfl_up_sync(0xffffffffu, x, o);
        if (lane >= o) x += y;
    }
    if (lane < NBLK) g_bbase[lane] = x - v;
    if (lane == 31) g_off[NN] = x;
}

__global__ __launch_bounds__(1024) void scan_write_kernel() {
    __shared__ int ws[32];
    const int tid = threadIdx.x, lane = tid & 31, wid = tid >> 5;
    int base = blockIdx.x * SCAN_TILE + tid * 4;
    int v[4] = {0, 0, 0, 0};
    if (base + 3 < NN) {
        int4 t = *(const int4*)(g_deg + base);
        v[0] = t.x; v[1] = t.y; v[2] = t.z; v[3] = t.w;
    } else {
#pragma unroll
        for (int j = 0; j < 4; j++) if (base + j < NN) v[j] = g_deg[base + j];
    }
    int tsum = v[0] + v[1] + v[2] + v[3];
    int x = tsum;
#pragma unroll
    for (int o = 1; o < 32; o <<= 1) {
        int y = __shfl_up_sync(0xffffffffu, x, o);
        if (lane >= o) x += y;
    }
    if (lane == 31) ws[wid] = x;
    __syncthreads();
    if (wid == 0) {
        int w = ws[lane];
        int xs = w;
#pragma unroll
        for (int o = 1; o < 32; o <<= 1) {
            int y = __shfl_up_sync(0xffffffffu, xs, o);
            if (lane >= o) xs += y;
        }
        ws[lane] = xs - w;
    }
    __syncthreads();
    int off = g_bbase[blockIdx.x] + ws[wid] + (x - tsum);
#pragma unroll
    for (int j = 0; j < 4; j++) {
        int i = base + j;
        if (i < NN) {
            g_off[i] = off;
            g_srcid[off] = i;
            g_cur[i] = off + 1;
        }
        off += v[j];
    }
}

__global__ void scatter_kernel(const int* __restrict__ ei) {
    int e = blockIdx.x * blockDim.x + threadIdx.x;
    if (e < EE) {
        int d = ei[EE + e];
        int p = atomicAdd(&g_cur[d], 1);
        g_srcid[p] = ei[e];
    }
}

// ---------------- 4) single-pass softmax-aggregation + epilogue ----------------
__device__ __forceinline__ float lrelu(float x) { return x >= 0.f ? x : NEG_SLOPE * x; }

__global__ __launch_bounds__(256) void smagg_kernel(const float* __restrict__ bias,
                                                    const float* __restrict__ prelu_a,
                                                    float* __restrict__ out) {
    int warp = (blockIdx.x * 256 + threadIdx.x) >> 5;
    int lane = threadIdx.x & 31;
    if (warp >= NN) return;
    const int node = warp;
    const int beg = g_off[node], end = g_off[node + 1];
    const int head = lane >> 3;

    float4 ad = *(const float4*)(g_adst + node * HH);
    float adh = (head == 0) ? ad.x : (head == 1) ? ad.y : (head == 2) ? ad.z : ad.w;

    float acc[8];
#pragma unroll
    for (int j = 0; j < 8; j++) acc[j] = 0.f;
    float esum = 0.f;

    const uint4* h4 = (const uint4*)g_h16;

    int i = beg;
    for (; i + 2 <= end; i += 2) {
        int sA = __ldg(&g_srcid[i]);
        int sB = __ldg(&g_srcid[i + 1]);
        float asA = __ldg(&g_asrc[sA * HH + head]);
        float asB = __ldg(&g_asrc[sB * HH + head]);
        uint4 hA = h4[(size_t)sA * 32 + lane];
        uint4 hB = h4[(size_t)sB * 32 + lane];
        float eA = __expf(lrelu(asA + adh));
        float eB = __expf(lrelu(asB + adh));
        esum += eA + eB;

        float2 p;
        p = __half22float2(*(__half2*)&hA.x); acc[0] = fmaf(eA, p.x, acc[0]); acc[1] = fmaf(eA, p.y, acc[1]);
        p = __half22float2(*(__half2*)&hA.y); acc[2] = fmaf(eA, p.x, acc[2]); acc[3] = fmaf(eA, p.y, acc[3]);
        p = __half22float2(*(__half2*)&hA.z); acc[4] = fmaf(eA, p.x, acc[4]); acc[5] = fmaf(eA, p.y, acc[5]);
        p = __half22float2(*(__half2*)&hA.w); acc[6] = fmaf(eA, p.x, acc[6]); acc[7] = fmaf(eA, p.y, acc[7]);
        p = __half22float2(*(__half2*)&hB.x); acc[0] = fmaf(eB, p.x, acc[0]); acc[1] = fmaf(eB, p.y, acc[1]);
        p = __half22float2(*(__half2*)&hB.y); acc[2] = fmaf(eB, p.x, acc[2]); acc[3] = fmaf(eB, p.y, acc[3]);
        p = __half22float2(*(__half2*)&hB.z); acc[4] = fmaf(eB, p.x, acc[4]); acc[5] = fmaf(eB, p.y, acc[5]);
        p = __half22float2(*(__half2*)&hB.w); acc[6] = fmaf(eB, p.x, acc[6]); acc[7] = fmaf(eB, p.y, acc[7]);
    }
    for (; i < end; i++) {
        int s = __ldg(&g_srcid[i]);
        float as = __ldg(&g_asrc[s * HH + head]);
        uint4 hv = h4[(size_t)s * 32 + lane];
        float e = __expf(lrelu(as + adh));
        esum += e;
        float2 p;
        p = __half22float2(*(__half2*)&hv.x); acc[0] = fmaf(e, p.x, acc[0]); acc[1] = fmaf(e, p.y, acc[1]);
        p = __half22float2(*(__half2*)&hv.y); acc[2] = fmaf(e, p.x, acc[2]); acc[3] = fmaf(e, p.y, acc[3]);
        p = __half22float2(*(__half2*)&hv.z); acc[4] = fmaf(e, p.x, acc[4]); acc[5] = fmaf(e, p.y, acc[5]);
        p = __half22float2(*(__half2*)&hv.w); acc[6] = fmaf(e, p.x, acc[6]); acc[7] = fmaf(e, p.y, acc[7]);
    }

    float inv = 1.f / (esum + 1e-16f);

    const float4* b4 = (const float4*)bias;
    float4 b0 = b4[lane * 2], b1 = b4[lane * 2 + 1];
    float pa = prelu_a[0];

    float o0 = fmaf(acc[0], inv, b0.x); o0 = o0 >= 0.f ? o0 : pa * o0;
    float o1 = fmaf(acc[1], inv, b0.y); o1 = o1 >= 0.f ? o1 : pa * o1;
    float o2 = fmaf(acc[2], inv, b0.z); o2 = o2 >= 0.f ? o2 : pa * o2;
    float o3 = fmaf(acc[3], inv, b0.w); o3 = o3 >= 0.f ? o3 : pa * o3;
    float o4 = fmaf(acc[4], inv, b1.x); o4 = o4 >= 0.f ? o4 : pa * o4;
    float o5 = fmaf(acc[5], inv, b1.y); o5 = o5 >= 0.f ? o5 : pa * o5;
    float o6 = fmaf(acc[6], inv, b1.z); o6 = o6 >= 0.f ? o6 : pa * o6;
    float o7 = fmaf(acc[7], inv, b1.w); o7 = o7 >= 0.f ? o7 : pa * o7;

    // evict-first streaming stores: keep g_h16 resident in L2 for the gather
    float4* out4 = (float4*)out;
    __stcs(&out4[node * (HC / 4) + lane * 2],     make_float4(o0, o1, o2, o3));
    __stcs(&out4[node * (HC / 4) + lane * 2 + 1], make_float4(o4, o5, o6, o7));
}

// ---------------- launch ----------------
extern "C" void kernel_launch(void* const* d_in, const int* in_sizes, int n_in,
                              void* d_out, int out_size) {
    const float* x       = (const float*)d_in[0];
    const int*   ei      = (const int*)d_in[1];
    const float* W       = (const float*)d_in[2];
    const float* att_src = (const float*)d_in[3];
    const float* att_dst = (const float*)d_in[4];
    const float* bias    = (const float*)d_in[5];
    const float* prelu_a = (const float*)d_in[6];
    float* out = (float*)d_out;

    static cudaStream_t s2;
    static cudaEvent_t evf, evw, evj;
    static bool init_done = false;
    if (!init_done) {
        cudaStreamCreateWithFlags(&s2, cudaStreamNonBlocking);
        cudaEventCreateWithFlags(&evf, cudaEventDisableTiming);
        cudaEventCreateWithFlags(&evw, cudaEventDisableTiming);
        cudaEventCreateWithFlags(&evj, cudaEventDisableTiming);
        cudaFuncSetAttribute(mma_gemm_kernel, cudaFuncAttributeMaxDynamicSharedMemorySize, GEMM_SMEM);
        init_done = true;
    }

    // fork: W^T then CSR build on side stream
    cudaEventRecord(evf, 0);
    cudaStreamWaitEvent(s2, evf, 0);
    wt_kernel<<<(KIN * HC + 255) / 256, 256, 0, s2>>>(W);
    cudaEventRecord(evw, s2);
    deg_init_kernel<<<(NN + 255) / 256, 256, 0, s2>>>();
    deg_count_kernel<<<(EE + 511) / 512, 512, 0, s2>>>(ei);
    degsum_kernel<<<NBLK, 1024, 0, s2>>>();
    bscan_kernel<<<1, 32, 0, s2>>>();
    scan_write_kernel<<<NBLK, 1024, 0, s2>>>();
    scatter_kernel<<<(EE + 511) / 512, 512, 0, s2>>>(ei);
    cudaEventRecord(evj, s2);

    // main stream: GEMM starts as soon as W^T is done
    cudaStreamWaitEvent(0, evw, 0);
    dim3 ggrid(2, (NN + 127) / 128);
    mma_gemm_kernel<<<ggrid, 256, GEMM_SMEM>>>(x, att_src, att_dst);

    // join, then single-pass softmax+aggregate
    cudaStreamWaitEvent(0, evj, 0);
    smagg_kernel<<<(NN * 32 + 255) / 256, 256>>>(bias, prelu_a, out);
}